// round 8
// baseline (speedup 1.0000x reference)
#include <cuda_runtime.h>
#include <cuda_bf16.h>
#include <cstdint>

#define NMAX 100000
#define NPAD 100128         // padded rows (multiple of 128)
#define EMAX 1600000
#define FDIM 128
#define GMAX 64
#define CLS  10

// ---- scratch (static device arrays; no cudaMalloc allowed) ----
__device__ float g_deg    [NMAX];
__device__ float g_dinv   [NMAX];
__device__ int   g_rcnt   [NMAX];
__device__ int   g_rowptr [NMAX + 1];
__device__ int   g_fill   [NMAX];
__device__ int   g_csrsrc [EMAX];
__device__ float g_csrw   [EMAX];
// bf16 hi/lo planes, k-interleaved order, 64 uint32 per row
__device__ uint32_t g_Xh [NPAD * 64];
__device__ uint32_t g_Xl [NPAD * 64];
__device__ uint32_t g_T1h[NPAD * 64];
__device__ uint32_t g_T1l[NPAD * 64];
__device__ uint32_t g_T2h[NPAD * 64];
__device__ uint32_t g_T2l[NPAD * 64];
__device__ uint32_t g_H1h[NPAD * 64];
__device__ uint32_t g_H1l[NPAD * 64];
__device__ uint32_t g_H2h[NPAD * 64];
__device__ uint32_t g_H2l[NPAD * 64];
__device__ float g_sums[GMAX * FDIM];
__device__ float g_cnt [GMAX];
// pre-converted weights: [layer][src][hi|lo], k-interleaved, pitch 136 bf16
__device__ __nv_bfloat16 g_Wc[3 * 3 * 34816];

// bf16-pair position of even k within a 16-col group (k-interleave permutation)
__host__ __device__ __forceinline__ int kpos_even(int k) {
    int p = (k >> 1) & 7;
    return (k >> 4) * 16 + ((p & 3) << 2) + ((p >> 2) << 1);
}

// ---- plane encode/decode ----
__device__ __forceinline__ float4 dec4(uint2 h, uint2 l) {
    float2 a = __bfloat1622float2(*(__nv_bfloat162*)&h.x);
    float2 b = __bfloat1622float2(*(__nv_bfloat162*)&h.y);
    float2 c = __bfloat1622float2(*(__nv_bfloat162*)&l.x);
    float2 d = __bfloat1622float2(*(__nv_bfloat162*)&l.y);
    return make_float4(a.x + c.x, a.y + c.y, b.x + d.x, b.y + d.y);
}
__device__ __forceinline__ void enc_pair(float2 v, uint32_t& h, uint32_t& l) {
    __nv_bfloat16 h0 = __float2bfloat16(v.x), h1 = __float2bfloat16(v.y);
    float l0 = v.x - __bfloat162float(h0), l1 = v.y - __bfloat162float(h1);
    union { __nv_bfloat162 b; uint32_t u; } t;
    t.b = __halves2bfloat162(h0, h1); h = t.u;
    t.b = __halves2bfloat162(__float2bfloat16(l0), __float2bfloat16(l1)); l = t.u;
}
__device__ __forceinline__ void enc4(float4 v, uint2& h, uint2& l) {
    enc_pair(make_float2(v.x, v.y), h.x, l.x);
    enc_pair(make_float2(v.z, v.w), h.y, l.y);
}

// ================= k1: degree + in-count (one edge pass) =================
__global__ void degcnt_kernel(const int* __restrict__ src, const int* __restrict__ dst, int E) {
    int e = blockIdx.x * blockDim.x + threadIdx.x;
    if (e < E) {
        atomicAdd(&g_deg[src[e]], 1.0f);
        atomicAdd(&g_rcnt[dst[e]], 1);
    }
}

// ================= k2: single-block scan -> rowptr, plus dinv =================
__global__ void monoscan_kernel(int n) {
    __shared__ int warpsum[32];
    __shared__ int runbase;
    const int t = threadIdx.x, lane = t & 31, wid = t >> 5;
    if (t == 0) { runbase = 0; g_rowptr[0] = 0; }
    for (int base = 0; base < n; base += 4096) {
        int i = base + t * 4;
        int4 v;
        if (i + 3 < n) v = *(const int4*)&g_rcnt[i];
        else v = make_int4(i < n ? g_rcnt[i] : 0, i + 1 < n ? g_rcnt[i+1] : 0,
                           i + 2 < n ? g_rcnt[i+2] : 0, i + 3 < n ? g_rcnt[i+3] : 0);
        int s0 = v.x, s1 = s0 + v.y, s2 = s1 + v.z, s3 = s2 + v.w;
        int sc = s3;
#pragma unroll
        for (int o = 1; o < 32; o <<= 1) {
            int u = __shfl_up_sync(0xffffffffu, sc, o);
            if (lane >= o) sc += u;
        }
        __syncthreads();                 // guard warpsum vs prior iter's reads
        if (lane == 31) warpsum[wid] = sc;
        __syncthreads();
        if (wid == 0) {
            int ws = warpsum[lane];
#pragma unroll
            for (int o = 1; o < 32; o <<= 1) {
                int u = __shfl_up_sync(0xffffffffu, ws, o);
                if (lane >= o) ws += u;
            }
            warpsum[lane] = ws;
        }
        __syncthreads();
        int excl = sc - s3 + (wid ? warpsum[wid - 1] : 0) + runbase;
        if (i < n)     g_rowptr[i + 1] = excl + s0;
        if (i + 1 < n) g_rowptr[i + 2] = excl + s1;
        if (i + 2 < n) g_rowptr[i + 3] = excl + s2;
        if (i + 3 < n) g_rowptr[i + 4] = excl + s3;
#pragma unroll
        for (int j = 0; j < 4; ++j) {
            if (i + j < n) {
                float d = g_deg[i + j];
                g_dinv[i + j] = (d > 0.0f) ? rsqrtf(d) : 0.0f;
            }
        }
        __syncthreads();
        if (t == 0) runbase += warpsum[31];
    }
}

// ================= k3: CSR fill + X -> bf16 hi/lo planes =================
__global__ void fillx_kernel(const int* __restrict__ src, const int* __restrict__ dst, int E,
                             const float4* __restrict__ X, int n) {
    int idx = blockIdx.x * blockDim.x + threadIdx.x;
    if (idx < E) {
        int d = dst[idx], s = src[idx];
        int p = g_rowptr[d] + atomicAdd(&g_fill[d], 1);
        g_csrsrc[p] = s;
        g_csrw[p]   = -g_dinv[s] * g_dinv[d];
    }
    if (idx < n * 32) {
        int row = idx >> 5;
        int c4  = (idx & 31) << 2;
        float4 v = __ldg(&X[idx]);
        uint32_t h0, l0, h1, l1;
        enc_pair(make_float2(v.x, v.y), h0, l0);
        enc_pair(make_float2(v.z, v.w), h1, l1);
        int p0 = kpos_even(c4) >> 1;
        int p1 = kpos_even(c4 + 2) >> 1;
        g_Xh[(size_t)row * 64 + p0] = h0; g_Xl[(size_t)row * 64 + p0] = l0;
        g_Xh[(size_t)row * 64 + p1] = h1; g_Xl[(size_t)row * 64 + p1] = l1;
    }
}

// ================= CSR propagation on planes: one warp per row =================
// MODE 0: O = Lhat*X ; MODE 1: O = 2*(Lhat*X) - X0
template <int MODE>
__global__ void prop_csr_kernel(const uint2* __restrict__ Xh, const uint2* __restrict__ Xl,
                                const uint2* __restrict__ X0h, const uint2* __restrict__ X0l,
                                uint2* __restrict__ Oh, uint2* __restrict__ Ol, int n) {
    int gw = (blockIdx.x * blockDim.x + threadIdx.x) >> 5;
    if (gw >= n) return;
    int lane = threadIdx.x & 31;
    int p    = __ldg(&g_rowptr[gw]);
    int end  = __ldg(&g_rowptr[gw + 1]);
    float4 acc = make_float4(0.f, 0.f, 0.f, 0.f);
    for (; p + 3 < end; p += 4) {
        int   s0 = __ldg(&g_csrsrc[p]),   s1 = __ldg(&g_csrsrc[p+1]);
        int   s2 = __ldg(&g_csrsrc[p+2]), s3 = __ldg(&g_csrsrc[p+3]);
        float w0 = __ldg(&g_csrw[p]),     w1 = __ldg(&g_csrw[p+1]);
        float w2 = __ldg(&g_csrw[p+2]),   w3 = __ldg(&g_csrw[p+3]);
        float4 v0 = dec4(__ldg(&Xh[(size_t)s0*32+lane]), __ldg(&Xl[(size_t)s0*32+lane]));
        float4 v1 = dec4(__ldg(&Xh[(size_t)s1*32+lane]), __ldg(&Xl[(size_t)s1*32+lane]));
        float4 v2 = dec4(__ldg(&Xh[(size_t)s2*32+lane]), __ldg(&Xl[(size_t)s2*32+lane]));
        float4 v3 = dec4(__ldg(&Xh[(size_t)s3*32+lane]), __ldg(&Xl[(size_t)s3*32+lane]));
        acc.x += w0*v0.x + w1*v1.x + w2*v2.x + w3*v3.x;
        acc.y += w0*v0.y + w1*v1.y + w2*v2.y + w3*v3.y;
        acc.z += w0*v0.z + w1*v1.z + w2*v2.z + w3*v3.z;
        acc.w += w0*v0.w + w1*v1.w + w2*v2.w + w3*v3.w;
    }
    for (; p < end; ++p) {
        int   s = __ldg(&g_csrsrc[p]);
        float w = __ldg(&g_csrw[p]);
        float4 v = dec4(__ldg(&Xh[(size_t)s*32+lane]), __ldg(&Xl[(size_t)s*32+lane]));
        acc.x += w*v.x; acc.y += w*v.y; acc.z += w*v.z; acc.w += w*v.w;
    }
    if (MODE == 1) {
        float4 u = dec4(__ldg(&X0h[(size_t)gw*32+lane]), __ldg(&X0l[(size_t)gw*32+lane]));
        acc.x = 2.f*acc.x - u.x; acc.y = 2.f*acc.y - u.y;
        acc.z = 2.f*acc.z - u.z; acc.w = 2.f*acc.w - u.w;
    }
    uint2 ho, lo;
    enc4(acc, ho, lo);
    Oh[(size_t)gw*32+lane] = ho;
    Ol[(size_t)gw*32+lane] = lo;
}

// ================= weight pre-conversion (all 3 layers, one launch) =================
__global__ void wcvt_kernel(const float* __restrict__ W1, const float* __restrict__ W2,
                            const float* __restrict__ W3, __nv_bfloat16* __restrict__ out) {
    int e = blockIdx.x * blockDim.x + threadIdx.x;
    if (e >= 9 * 16384) return;
    int L = e / 49152;
    int r = e % 49152;
    const float* W = (L == 0) ? W1 : (L == 1) ? W2 : W3;
    int s  = r >> 14;
    int rr = r & 16383;
    int k  = rr >> 7;
    int nn = rr & 127;
    float v = W[s * 16384 + k * 128 + nn];
    __nv_bfloat16 h = __float2bfloat16(v);
    __nv_bfloat16 l = __float2bfloat16(v - __bfloat162float(h));
    int pos = kpos_even(k & ~1) + (k & 1);
    __nv_bfloat16* o = out + (size_t)L * 3 * 34816 + (size_t)s * 34816 + nn * 136 + pos;
    o[0]     = h;
    o[17408] = l;
}

// ================= bf16 mma.sync GEMM (A pre-converted planes, cp.async staging) ====
// BM=128, BN=128, 8 warps (4M x 2N), warp tile 32x64. 1 CTA/SM.
// MODE 0: write H planes (relu). MODE 2: red.global into g_sums[batch[row]] (natural cols).
#define APITCH 272
#define SMA_HI 0
#define SMA_LO (128 * APITCH)
#define SMW_HI (2 * 128 * APITCH)
#define SMW_LO (3 * 128 * APITCH)
#define SM_GEMM (4 * 128 * APITCH)

__device__ __forceinline__ uint32_t smem_u32(const void* p) {
    uint32_t a;
    asm("{ .reg .u64 t; cvta.to.shared.u64 t, %1; cvt.u32.u64 %0, t; }" : "=r"(a) : "l"(p));
    return a;
}
__device__ __forceinline__ void mma_bf16(float& d0, float& d1, float& d2, float& d3,
                                         uint32_t a0, uint32_t a1, uint32_t a2, uint32_t a3,
                                         uint32_t b0, uint32_t b1) {
    asm volatile("mma.sync.aligned.m16n8k16.row.col.f32.bf16.bf16.f32 "
                 "{%0,%1,%2,%3}, {%4,%5,%6,%7}, {%8,%9}, {%0,%1,%2,%3};"
                 : "+f"(d0), "+f"(d1), "+f"(d2), "+f"(d3)
                 : "r"(a0), "r"(a1), "r"(a2), "r"(a3), "r"(b0), "r"(b1));
}

template <int MODE>
__global__ void __launch_bounds__(256, 1) gemm_mma_kernel(
    const uint32_t* __restrict__ A0h, const uint32_t* __restrict__ A0l,
    const uint32_t* __restrict__ A1h, const uint32_t* __restrict__ A1l,
    const uint32_t* __restrict__ A2h, const uint32_t* __restrict__ A2l,
    const __nv_bfloat16* __restrict__ Wc, const float* __restrict__ bias,
    uint32_t* __restrict__ OUTh, uint32_t* __restrict__ OUTl,
    const int* __restrict__ batch, int n)
{
    extern __shared__ __align__(16) char smem[];
    const int tid  = threadIdx.x;
    const int wid  = tid >> 5;
    const int lane = tid & 31;
    const int wm   = wid & 3;
    const int wn   = wid >> 2;
    const int row0 = blockIdx.x * 128;

    float acc[2][8][4];
#pragma unroll
    for (int i = 0; i < 2; ++i)
#pragma unroll
        for (int j = 0; j < 8; ++j)
#pragma unroll
            for (int c = 0; c < 4; ++c) acc[i][j][c] = 0.0f;

    const uint32_t smaH = smem_u32(smem + SMA_HI);
    const uint32_t smaL = smem_u32(smem + SMA_LO);
    const uint32_t smw  = smem_u32(smem + SMW_HI);

    for (int s = 0; s < 3; ++s) {
        const uint32_t* Ah = (s == 0) ? A0h : (s == 1) ? A1h : A2h;
        const uint32_t* Al = (s == 0) ? A0l : (s == 1) ? A1l : A2l;
        __syncthreads();
        // W planes: contiguous copy (layout already final)
        {
            const char* wsrc = (const char*)(Wc + (size_t)s * 34816);
#pragma unroll
            for (int i = 0; i < 17; ++i) {
                uint32_t dp = smw + (i * 256 + tid) * 16;
                const char* sp = wsrc + (i * 256 + tid) * 16;
                asm volatile("cp.async.cg.shared.global [%0], [%1], 16;" :: "r"(dp), "l"(sp));
            }
        }
        // A planes: 256B global rows -> 272B smem pitch
        {
            const char* ah = (const char*)Ah + (size_t)row0 * 256;
            const char* al = (const char*)Al + (size_t)row0 * 256;
#pragma unroll
            for (int i = 0; i < 8; ++i) {
                int q = i * 256 + tid;
                uint32_t od = (uint32_t)((q >> 4) * APITCH + (q & 15) * 16);
                asm volatile("cp.async.cg.shared.global [%0], [%1], 16;"
                             :: "r"(smaH + od), "l"(ah + q * 16));
                asm volatile("cp.async.cg.shared.global [%0], [%1], 16;"
                             :: "r"(smaL + od), "l"(al + q * 16));
            }
        }
        asm volatile("cp.async.commit_group;" ::: "memory");
        asm volatile("cp.async.wait_group 0;" ::: "memory");
        __syncthreads();

        // fused precision loop: Ah*Wh + Al*Wh + Ah*Wl
        {
            const char* ah0 = smem + SMA_HI + (wm * 32 + (lane >> 2)) * APITCH + (lane & 3) * 8;
            const char* al0 = smem + SMA_LO + (wm * 32 + (lane >> 2)) * APITCH + (lane & 3) * 8;
            const char* bh0 = smem + SMW_HI + (wn * 64 + (lane >> 2)) * APITCH + (lane & 3) * 8;
            const char* bl0 = smem + SMW_LO + (wn * 64 + (lane >> 2)) * APITCH + (lane & 3) * 8;
#pragma unroll
            for (int g = 0; g < 8; ++g) {
                const int go = g * 32;
                uint2 ah[4], al[4], bh[8], bl[8];
#pragma unroll
                for (int r = 0; r < 4; ++r) {
                    ah[r] = *(const uint2*)(ah0 + r * 8 * APITCH + go);
                    al[r] = *(const uint2*)(al0 + r * 8 * APITCH + go);
                }
#pragma unroll
                for (int j = 0; j < 8; ++j) {
                    bh[j] = *(const uint2*)(bh0 + j * 8 * APITCH + go);
                    bl[j] = *(const uint2*)(bl0 + j * 8 * APITCH + go);
                }
#pragma unroll
                for (int j = 0; j < 8; ++j) {
                    mma_bf16(acc[0][j][0], acc[0][j][1], acc[0][j][2], acc[0][j][3],
                             ah[0].x, ah[1].x, ah[0].y, ah[1].y, bh[j].x, bh[j].y);
                    mma_bf16(acc[1][j][0], acc[1][j][1], acc[1][j][2], acc[1][j][3],
                             ah[2].x, ah[3].x, ah[2].y, ah[3].y, bh[j].x, bh[j].y);
                    mma_bf16(acc[0][j][0], acc[0][j][1], acc[0][j][2], acc[0][j][3],
                             al[0].x, al[1].x, al[0].y, al[1].y, bh[j].x, bh[j].y);
                    mma_bf16(acc[1][j][0], acc[1][j][1], acc[1][j][2], acc[1][j][3],
                             al[2].x, al[3].x, al[2].y, al[3].y, bh[j].x, bh[j].y);
                    mma_bf16(acc[0][j][0], acc[0][j][1], acc[0][j][2], acc[0][j][3],
                             ah[0].x, ah[1].x, ah[0].y, ah[1].y, bl[j].x, bl[j].y);
                    mma_bf16(acc[1][j][0], acc[1][j][1], acc[1][j][2], acc[1][j][3],
                             ah[2].x, ah[3].x, ah[2].y, ah[3].y, bl[j].x, bl[j].y);
                }
            }
        }
    }

    // ---- epilogue ----
#pragma unroll
    for (int i = 0; i < 2; ++i) {
        int r0 = row0 + wm * 32 + i * 16 + (lane >> 2);
        int r1 = r0 + 8;
        int g0 = 0, g1 = 0;
        if (MODE == 2) {
            if (r0 < n) g0 = __ldg(&batch[r0]);
            if (r1 < n) g1 = __ldg(&batch[r1]);
        }
#pragma unroll
        for (int j = 0; j < 8; ++j) {
            int col = wn * 64 + j * 8 + (lane & 3) * 2;
            float2 bv = __ldg((const float2*)&bias[col]);
            float2 o0 = make_float2(acc[i][j][0] + bv.x, acc[i][j][1] + bv.y);
            float2 o1 = make_float2(acc[i][j][2] + bv.x, acc[i][j][3] + bv.y);
            if (MODE == 0) {
                o0.x = fmaxf(o0.x, 0.f); o0.y = fmaxf(o0.y, 0.f);
                o1.x = fmaxf(o1.x, 0.f); o1.y = fmaxf(o1.y, 0.f);
                int pos = kpos_even(col) >> 1;
                uint32_t h, l;
                if (r0 < n) {
                    enc_pair(o0, h, l);
                    OUTh[(size_t)r0 * 64 + pos] = h;
                    OUTl[(size_t)r0 * 64 + pos] = l;
                }
                if (r1 < n) {
                    enc_pair(o1, h, l);
                    OUTh[(size_t)r1 * 64 + pos] = h;
                    OUTl[(size_t)r1 * 64 + pos] = l;
                }
            } else {
                if (r0 < n) {
                    float* p = &g_sums[g0 * FDIM + col];
                    asm volatile("red.global.add.v2.f32 [%0], {%1,%2};"
                                 :: "l"(p), "f"(o0.x), "f"(o0.y) : "memory");
                }
                if (r1 < n) {
                    float* p = &g_sums[g1 * FDIM + col];
                    asm volatile("red.global.add.v2.f32 [%0], {%1,%2};"
                                 :: "l"(p), "f"(o1.x), "f"(o1.y) : "memory");
                }
            }
        }
    }
}

// ================= pooling counts + classifier =================
__global__ void cnt_kernel(const int* __restrict__ batch, int n) {
    int i = blockIdx.x * blockDim.x + threadIdx.x;
    if (i < n) atomicAdd(&g_cnt[batch[i]], 1.0f);
}
__global__ void final_kernel(const float* __restrict__ Wl, const float* __restrict__ bl,
                             float* __restrict__ out, int ngraphs) {
    int tid = blockIdx.x * blockDim.x + threadIdx.x;
    if (tid >= ngraphs * CLS) return;
    int g = tid / CLS;
    int c = tid % CLS;
    float s = 0.0f;
    const float* sp = &g_sums[g * FDIM];
#pragma unroll 16
    for (int d = 0; d < FDIM; ++d) s = fmaf(sp[d], Wl[d * CLS + c], s);
    float cnt = fmaxf(g_cnt[g], 1.0f);
    out[g * CLS + c] = s / cnt + bl[c];
}

// ---------------------------------------------------------------
extern "C" void kernel_launch(void* const* d_in, const int* in_sizes, int n_in,
                              void* d_out, int out_size) {
    const float* x   = (const float*)d_in[0];
    const int*   ei  = (const int*)  d_in[1];
    const int*   bat = (const int*)  d_in[2];
    const float* W1  = (const float*)d_in[3];
    const float* b1  = (const float*)d_in[4];
    const float* W2  = (const float*)d_in[5];
    const float* b2  = (const float*)d_in[6];
    const float* W3  = (const float*)d_in[7];
    const float* b3  = (const float*)d_in[8];
    const float* Wl  = (const float*)d_in[9];
    const float* bl  = (const float*)d_in[10];
    float* out = (float*)d_out;

    const int n = in_sizes[0] / FDIM;          // 100000
    const int E = in_sizes[1] / 2;             // 1600000
    const int G = out_size / CLS;              // 64
    const int* src = ei;
    const int* dst = ei + E;
    const int ntiles = (n + 127) / 128;

    float *deg, *sums, *cnt;
    int *rcnt, *fill;
    uint32_t *Xh, *Xl, *T1h, *T1l, *T2h, *T2l, *H1h, *H1l, *H2h, *H2l;
    __nv_bfloat16* Wc;
    cudaGetSymbolAddress((void**)&deg,  g_deg);
    cudaGetSymbolAddress((void**)&rcnt, g_rcnt);
    cudaGetSymbolAddress((void**)&fill, g_fill);
    cudaGetSymbolAddress((void**)&Xh,  g_Xh);  cudaGetSymbolAddress((void**)&Xl,  g_Xl);
    cudaGetSymbolAddress((void**)&T1h, g_T1h); cudaGetSymbolAddress((void**)&T1l, g_T1l);
    cudaGetSymbolAddress((void**)&T2h, g_T2h); cudaGetSymbolAddress((void**)&T2l, g_T2l);
    cudaGetSymbolAddress((void**)&H1h, g_H1h); cudaGetSymbolAddress((void**)&H1l, g_H1l);
    cudaGetSymbolAddress((void**)&H2h, g_H2h); cudaGetSymbolAddress((void**)&H2l, g_H2l);
    cudaGetSymbolAddress((void**)&sums, g_sums);
    cudaGetSymbolAddress((void**)&cnt,  g_cnt);
    cudaGetSymbolAddress((void**)&Wc,   g_Wc);

    cudaFuncSetAttribute(gemm_mma_kernel<0>, cudaFuncAttributeMaxDynamicSharedMemorySize, SM_GEMM);
    cudaFuncSetAttribute(gemm_mma_kernel<2>, cudaFuncAttributeMaxDynamicSharedMemorySize, SM_GEMM);

    const int TB = 256;

    cudaMemsetAsync(deg,  0, (size_t)n * sizeof(float));
    cudaMemsetAsync(rcnt, 0, (size_t)n * sizeof(int));
    cudaMemsetAsync(fill, 0, (size_t)n * sizeof(int));
    cudaMemsetAsync(sums, 0, (size_t)G * FDIM * sizeof(float));
    cudaMemsetAsync(cnt,  0, (size_t)G * sizeof(float));

    // k1..k3: prepass (minimal chain so prop1 is the 4th kernel for ncu)
    degcnt_kernel<<<(E + TB - 1) / TB, TB>>>(src, dst, E);
    monoscan_kernel<<<1, 1024>>>(n);
    {
        int work = (E > n * 32) ? E : n * 32;
        fillx_kernel<<<(work + TB - 1) / TB, TB>>>(src, dst, E, (const float4*)x, n);
    }

    const int propBlocks = (n * 32 + TB - 1) / TB;

    // k4/k5: layer-1 props (k4 gets profiled)
    prop_csr_kernel<0><<<propBlocks, TB>>>((const uint2*)Xh, (const uint2*)Xl,
                                           nullptr, nullptr, (uint2*)T1h, (uint2*)T1l, n);
    prop_csr_kernel<1><<<propBlocks, TB>>>((const uint2*)T1h, (const uint2*)T1l,
                                           (const uint2*)Xh, (const uint2*)Xl,
                                           (uint2*)T2h, (uint2*)T2l, n);
    // k6/k7: weight conversion + graph counts (needed before gemm1/final)
    wcvt_kernel<<<(9 * 16384 + TB - 1) / TB, TB>>>(W1, W2, W3, Wc);
    cnt_kernel<<<(n + TB - 1) / TB, TB>>>(bat, n);

    // layer 1 GEMM
    gemm_mma_kernel<0><<<ntiles, 256, SM_GEMM>>>(Xh, Xl, T1h, T1l, T2h, T2l,
                                                 Wc, b1, H1h, H1l, nullptr, n);
    // layer 2
    prop_csr_kernel<0><<<propBlocks, TB>>>((const uint2*)H1h, (const uint2*)H1l,
                                           nullptr, nullptr, (uint2*)T1h, (uint2*)T1l, n);
    prop_csr_kernel<1><<<propBlocks, TB>>>((const uint2*)T1h, (const uint2*)T1l,
                                           (const uint2*)H1h, (const uint2*)H1l,
                                           (uint2*)T2h, (uint2*)T2l, n);
    gemm_mma_kernel<0><<<ntiles, 256, SM_GEMM>>>(H1h, H1l, T1h, T1l, T2h, T2l,
                                                 Wc + (size_t)3 * 34816, b2, H2h, H2l, nullptr, n);
    // layer 3 (pool fused into epilogue, natural column order in g_sums)
    prop_csr_kernel<0><<<propBlocks, TB>>>((const uint2*)H2h, (const uint2*)H2l,
                                           nullptr, nullptr, (uint2*)T1h, (uint2*)T1l, n);
    prop_csr_kernel<1><<<propBlocks, TB>>>((const uint2*)T1h, (const uint2*)T1l,
                                           (const uint2*)H2h, (const uint2*)H2l,
                                           (uint2*)T2h, (uint2*)T2l, n);
    gemm_mma_kernel<2><<<ntiles, 256, SM_GEMM>>>(H2h, H2l, T1h, T1l, T2h, T2l,
                                                 Wc + (size_t)6 * 34816, b3, nullptr, nullptr, bat, n);

    // classifier
    final_kernel<<<(G * CLS + TB - 1) / TB, TB>>>(Wl, bl, out, G);
}

// round 9
// speedup vs baseline: 1.1085x; 1.1085x over previous
#include <cuda_runtime.h>
#include <cuda_bf16.h>
#include <cstdint>

#define NMAX 100000
#define NPAD 100128
#define EMAX 1600000
#define FDIM 128
#define GMAX 64
#define CLS  10
#define SCAN_B 1024

// ---- scratch ----
__device__ float g_deg    [NMAX];
__device__ float g_dinv   [NMAX];
__device__ int   g_rcnt   [NMAX];
__device__ int   g_incl   [NMAX];
__device__ int   g_part   [256];
__device__ int   g_rowptr [NMAX + 1];
__device__ int   g_fill   [NMAX];
__device__ int   g_csrsrc [EMAX];
__device__ float g_csrw   [EMAX];
// combined bf16 hi/lo planes: row = 512B = 8 groups x [4 granules x (hi u2 | lo u2)]
__device__ uint32_t g_X [NPAD * 128];
__device__ uint32_t g_T1[NPAD * 128];
__device__ uint32_t g_T2[NPAD * 128];
__device__ uint32_t g_H1[NPAD * 128];
__device__ uint32_t g_H2[NPAD * 128];
__device__ float g_sums[GMAX * FDIM];
__device__ float g_cnt [GMAX];
// weights: [layer][src] 128 n-rows x 512B, same interleaved layout
__device__ uint32_t g_Wc[9 * 16384];

// byte offset (within a 512B row) of the u32 holding cols (c, c+1); lo plane at +8
__host__ __device__ __forceinline__ int posu32(int c) {
    int grp = c >> 4, pg = (c >> 1) & 7;
    return grp * 64 + (pg & 3) * 16 + (pg >> 2) * 4;
}

__device__ __forceinline__ float4 dec4(uint4 v) {
    float a0 = __uint_as_float(v.x << 16)          + __uint_as_float(v.z << 16);
    float a1 = __uint_as_float(v.x & 0xffff0000u)  + __uint_as_float(v.z & 0xffff0000u);
    float a2 = __uint_as_float(v.y << 16)          + __uint_as_float(v.w << 16);
    float a3 = __uint_as_float(v.y & 0xffff0000u)  + __uint_as_float(v.w & 0xffff0000u);
    return make_float4(a0, a1, a2, a3);
}
__device__ __forceinline__ void enc_pair(float2 v, uint32_t& h, uint32_t& l) {
    __nv_bfloat16 h0 = __float2bfloat16(v.x), h1 = __float2bfloat16(v.y);
    float l0 = v.x - __bfloat162float(h0), l1 = v.y - __bfloat162float(h1);
    union { __nv_bfloat162 b; uint32_t u; } t;
    t.b = __halves2bfloat162(h0, h1); h = t.u;
    t.b = __halves2bfloat162(__float2bfloat16(l0), __float2bfloat16(l1)); l = t.u;
}
__device__ __forceinline__ uint4 enc4(float4 f) {
    uint4 o;
    enc_pair(make_float2(f.x, f.y), o.x, o.z);
    enc_pair(make_float2(f.z, f.w), o.y, o.w);
    return o;
}

// ================= prepass =================
__global__ void degcnt_kernel(const int* __restrict__ src, const int* __restrict__ dst, int E) {
    int e = blockIdx.x * blockDim.x + threadIdx.x;
    if (e < E) {
        atomicAdd(&g_deg[src[e]], 1.0f);
        atomicAdd(&g_rcnt[dst[e]], 1);
    }
}
__global__ void scan1_kernel(int n) {
    __shared__ int sm[SCAN_B];
    int i = blockIdx.x * SCAN_B + threadIdx.x;
    int v = (i < n) ? g_rcnt[i] : 0;
    sm[threadIdx.x] = v;
    __syncthreads();
    for (int off = 1; off < SCAN_B; off <<= 1) {
        int t = (threadIdx.x >= off) ? sm[threadIdx.x - off] : 0;
        __syncthreads();
        sm[threadIdx.x] += t;
        __syncthreads();
    }
    if (i < n) g_incl[i] = sm[threadIdx.x];
    if (threadIdx.x == SCAN_B - 1) g_part[blockIdx.x] = sm[threadIdx.x];
}
__global__ void scan2_kernel(int nb) {
    __shared__ int sm[256];
    int v = (threadIdx.x < nb) ? g_part[threadIdx.x] : 0;
    sm[threadIdx.x] = v;
    __syncthreads();
    for (int off = 1; off < 256; off <<= 1) {
        int t = (threadIdx.x >= off) ? sm[threadIdx.x - off] : 0;
        __syncthreads();
        sm[threadIdx.x] += t;
        __syncthreads();
    }
    if (threadIdx.x < nb) g_part[threadIdx.x] = sm[threadIdx.x] - v;
}
__global__ void scan3_kernel(int n) {   // rowptr + dinv
    int i = blockIdx.x * blockDim.x + threadIdx.x;
    if (i < n) {
        g_rowptr[i + 1] = g_incl[i] + g_part[i / SCAN_B];
        float d = g_deg[i];
        g_dinv[i] = (d > 0.0f) ? rsqrtf(d) : 0.0f;
    }
    if (i == 0) g_rowptr[0] = 0;
}
// CSR fill + X -> interleaved planes
__global__ void fillx_kernel(const int* __restrict__ src, const int* __restrict__ dst, int E,
                             const float4* __restrict__ X, int n) {
    int idx = blockIdx.x * blockDim.x + threadIdx.x;
    if (idx < E) {
        int d = dst[idx], s = src[idx];
        int p = g_rowptr[d] + atomicAdd(&g_fill[d], 1);
        g_csrsrc[p] = s;
        g_csrw[p]   = -g_dinv[s] * g_dinv[d];
    }
    if (idx < n * 32) {
        int row = idx >> 5;
        int c4  = (idx & 31) << 2;
        float4 v = __ldg(&X[idx]);
        uint32_t h0, l0, h1, l1;
        enc_pair(make_float2(v.x, v.y), h0, l0);
        enc_pair(make_float2(v.z, v.w), h1, l1);
        char* xr = (char*)g_X + (size_t)row * 512;
        int p0 = posu32(c4), p1 = posu32(c4 + 2);
        *(uint32_t*)(xr + p0)     = h0;
        *(uint32_t*)(xr + p0 + 8) = l0;
        *(uint32_t*)(xr + p1)     = h1;
        *(uint32_t*)(xr + p1 + 8) = l1;
    }
}

// ================= CSR propagation: one warp per row, LDG.128 gathers ============
// MODE 0: O = Lhat*X ; MODE 1: O = 2*(Lhat*X) - X0
template <int MODE>
__global__ void __launch_bounds__(256) prop_csr_kernel(
    const uint4* __restrict__ X, const uint4* __restrict__ X0, uint4* __restrict__ O, int n) {
    int gw = (blockIdx.x * blockDim.x + threadIdx.x) >> 5;
    if (gw >= n) return;
    int lane = threadIdx.x & 31;
    int p    = __ldg(&g_rowptr[gw]);
    int end  = __ldg(&g_rowptr[gw + 1]);
    float4 acc = make_float4(0.f, 0.f, 0.f, 0.f);
    for (; p + 3 < end; p += 4) {
        int   s0 = __ldg(&g_csrsrc[p]),   s1 = __ldg(&g_csrsrc[p+1]);
        int   s2 = __ldg(&g_csrsrc[p+2]), s3 = __ldg(&g_csrsrc[p+3]);
        float w0 = __ldg(&g_csrw[p]),     w1 = __ldg(&g_csrw[p+1]);
        float w2 = __ldg(&g_csrw[p+2]),   w3 = __ldg(&g_csrw[p+3]);
        float4 v0 = dec4(__ldg(&X[(size_t)s0 * 32 + lane]));
        float4 v1 = dec4(__ldg(&X[(size_t)s1 * 32 + lane]));
        float4 v2 = dec4(__ldg(&X[(size_t)s2 * 32 + lane]));
        float4 v3 = dec4(__ldg(&X[(size_t)s3 * 32 + lane]));
        acc.x += w0*v0.x + w1*v1.x + w2*v2.x + w3*v3.x;
        acc.y += w0*v0.y + w1*v1.y + w2*v2.y + w3*v3.y;
        acc.z += w0*v0.z + w1*v1.z + w2*v2.z + w3*v3.z;
        acc.w += w0*v0.w + w1*v1.w + w2*v2.w + w3*v3.w;
    }
    for (; p < end; ++p) {
        int   s = __ldg(&g_csrsrc[p]);
        float w = __ldg(&g_csrw[p]);
        float4 v = dec4(__ldg(&X[(size_t)s * 32 + lane]));
        acc.x += w*v.x; acc.y += w*v.y; acc.z += w*v.z; acc.w += w*v.w;
    }
    if (MODE == 1) {
        float4 u = dec4(__ldg(&X0[(size_t)gw * 32 + lane]));
        acc.x = 2.f*acc.x - u.x; acc.y = 2.f*acc.y - u.y;
        acc.z = 2.f*acc.z - u.z; acc.w = 2.f*acc.w - u.w;
    }
    O[(size_t)gw * 32 + lane] = enc4(acc);
}

// ================= weight pre-conversion =================
__global__ void wcvt_kernel(const float* __restrict__ W1, const float* __restrict__ W2,
                            const float* __restrict__ W3, uint32_t* __restrict__ out) {
    int e = blockIdx.x * blockDim.x + threadIdx.x;
    if (e >= 9 * 8192) return;
    int L  = e / 24576;
    int r  = e % 24576;
    int s  = r >> 13;
    int rr = r & 8191;
    int p  = rr >> 7;        // pair 0..63
    int nn = rr & 127;
    const float* W = (L == 0) ? W1 : (L == 1) ? W2 : W3;
    int k = 2 * p;
    float v0 = W[s * 16384 + k * 128 + nn];
    float v1 = W[s * 16384 + (k + 1) * 128 + nn];
    uint32_t h, l;
    enc_pair(make_float2(v0, v1), h, l);
    char* o = (char*)out + ((size_t)(L * 3 + s) * 128 + nn) * 512;
    int pos = posu32(k);
    *(uint32_t*)(o + pos)     = h;
    *(uint32_t*)(o + pos + 8) = l;
}

// ================= bf16 mma.sync GEMM =================
// BM=BN=128, 8 warps (4M x 2N), warp tile 32x64, interleaved hi/lo fragments (LDS.128).
#define SPITCH 576
#define SMW_OFF (128 * SPITCH)
#define SM_GEMM (2 * 128 * SPITCH)      // 147456

__device__ __forceinline__ uint32_t smem_u32(const void* p) {
    uint32_t a;
    asm("{ .reg .u64 t; cvta.to.shared.u64 t, %1; cvt.u32.u64 %0, t; }" : "=r"(a) : "l"(p));
    return a;
}
__device__ __forceinline__ void mma_bf16(float& d0, float& d1, float& d2, float& d3,
                                         uint32_t a0, uint32_t a1, uint32_t a2, uint32_t a3,
                                         uint32_t b0, uint32_t b1) {
    asm volatile("mma.sync.aligned.m16n8k16.row.col.f32.bf16.bf16.f32 "
                 "{%0,%1,%2,%3}, {%4,%5,%6,%7}, {%8,%9}, {%0,%1,%2,%3};"
                 : "+f"(d0), "+f"(d1), "+f"(d2), "+f"(d3)
                 : "r"(a0), "r"(a1), "r"(a2), "r"(a3), "r"(b0), "r"(b1));
}

template <int MODE>
__global__ void __launch_bounds__(256, 1) gemm_mma_kernel(
    const uint32_t* __restrict__ A0, const uint32_t* __restrict__ A1,
    const uint32_t* __restrict__ A2,
    const uint32_t* __restrict__ Wc, const float* __restrict__ bias,
    uint32_t* __restrict__ OUT, const int* __restrict__ batch, int n)
{
    extern __shared__ __align__(16) char smem[];
    const int tid  = threadIdx.x;
    const int wid  = tid >> 5;
    const int lane = tid & 31;
    const int wm   = wid & 3;
    const int wn   = wid >> 2;
    const int row0 = blockIdx.x * 128;

    float acc[2][8][4];
#pragma unroll
    for (int i = 0; i < 2; ++i)
#pragma unroll
        for (int j = 0; j < 8; ++j)
#pragma unroll
            for (int c = 0; c < 4; ++c) acc[i][j][c] = 0.0f;

    const uint32_t smA = smem_u32(smem);
    const uint32_t smW = smem_u32(smem + SMW_OFF);

    for (int s = 0; s < 3; ++s) {
        const uint32_t* A = (s == 0) ? A0 : (s == 1) ? A1 : A2;
        __syncthreads();
        // stage A: 128 rows x 512B contiguous -> pitch 576
        {
            const char* asrc = (const char*)A + (size_t)row0 * 512;
#pragma unroll
            for (int i = 0; i < 16; ++i) {
                int q = i * 256 + tid;
                uint32_t od = (uint32_t)((q >> 5) * SPITCH + (q & 31) * 16);
                asm volatile("cp.async.cg.shared.global [%0], [%1], 16;"
                             :: "r"(smA + od), "l"(asrc + q * 16));
            }
        }
        // stage W: 64KB contiguous -> pitch 576
        {
            const char* wsrc = (const char*)(Wc + (size_t)s * 16384);
#pragma unroll
            for (int i = 0; i < 16; ++i) {
                int q = i * 256 + tid;
                uint32_t od = (uint32_t)((q >> 5) * SPITCH + (q & 31) * 16);
                asm volatile("cp.async.cg.shared.global [%0], [%1], 16;"
                             :: "r"(smW + od), "l"(wsrc + q * 16));
            }
        }
        asm volatile("cp.async.commit_group;" ::: "memory");
        asm volatile("cp.async.wait_group 0;" ::: "memory");
        __syncthreads();

        // fused precision loop: Ah*Wh + Al*Wh + Ah*Wl  (hi/lo in one LDS.128)
        {
            const char* a0 = smem + (wm * 32 + (lane >> 2)) * SPITCH + (lane & 3) * 16;
            const char* b0 = smem + SMW_OFF + (wn * 64 + (lane >> 2)) * SPITCH + (lane & 3) * 16;
#pragma unroll
            for (int g = 0; g < 8; ++g) {
                const int go = g * 64;
                uint4 va[4], vb[8];
#pragma unroll
                for (int r = 0; r < 4; ++r)
                    va[r] = *(const uint4*)(a0 + r * 8 * SPITCH + go);
#pragma unroll
                for (int j = 0; j < 8; ++j)
                    vb[j] = *(const uint4*)(b0 + j * 8 * SPITCH + go);
#pragma unroll
                for (int j = 0; j < 8; ++j) {
                    // Ah*Wh
                    mma_bf16(acc[0][j][0], acc[0][j][1], acc[0][j][2], acc[0][j][3],
                             va[0].x, va[1].x, va[0].y, va[1].y, vb[j].x, vb[j].y);
                    mma_bf16(acc[1][j][0], acc[1][j][1], acc[1][j][2], acc[1][j][3],
                             va[2].x, va[3].x, va[2].y, va[3].y, vb[j].x, vb[j].y);
                    // Al*Wh
                    mma_bf16(acc[0][j][0], acc[0][j][1], acc[0][j][2], acc[0][j][3],
                             va[0].z, va[1].z, va[0].w, va[1].w, vb[j].x, vb[j].y);
                    mma_bf16(acc[1][j][0], acc[1][j][1], acc[1][j][2], acc[1][j][3],
                             va[2].z, va[3].z, va[2].w, va[3].w, vb[j].x, vb[j].y);
                    // Ah*Wl
                    mma_bf16(acc[0][j][0], acc[0][j][1], acc[0][j][2], acc[0][j][3],
                             va[0].x, va[1].x, va[0].y, va[1].y, vb[j].z, vb[j].w);
                    mma_bf16(acc[1][j][0], acc[1][j][1], acc[1][j][2], acc[1][j][3],
                             va[2].x, va[3].x, va[2].y, va[3].y, vb[j].z, vb[j].w);
                }
            }
        }
    }

    // ---- epilogue ----
#pragma unroll
    for (int i = 0; i < 2; ++i) {
        int r0 = row0 + wm * 32 + i * 16 + (lane >> 2);
        int r1 = r0 + 8;
        int g0 = 0, g1 = 0;
        if (MODE == 2) {
            if (r0 < n) g0 = __ldg(&batch[r0]);
            if (r1 < n) g1 = __ldg(&batch[r1]);
        }
#pragma unroll
        for (int j = 0; j < 8; ++j) {
            int col = wn * 64 + j * 8 + (lane & 3) * 2;
            float2 bv = __ldg((const float2*)&bias[col]);
            float2 o0 = make_float2(acc[i][j][0] + bv.x, acc[i][j][1] + bv.y);
            float2 o1 = make_float2(acc[i][j][2] + bv.x, acc[i][j][3] + bv.y);
            if (MODE == 0) {
                o0.x = fmaxf(o0.x, 0.f); o0.y = fmaxf(o0.y, 0.f);
                o1.x = fmaxf(o1.x, 0.f); o1.y = fmaxf(o1.y, 0.f);
                int pos = posu32(col);
                uint32_t h, l;
                if (r0 < n) {
                    enc_pair(o0, h, l);
                    char* orow = (char*)OUT + (size_t)r0 * 512;
                    *(uint32_t*)(orow + pos)     = h;
                    *(uint32_t*)(orow + pos + 8) = l;
                }
                if (r1 < n) {
                    enc_pair(o1, h, l);
                    char* orow = (char*)OUT + (size_t)r1 * 512;
                    *(uint32_t*)(orow + pos)     = h;
                    *(uint32_t*)(orow + pos + 8) = l;
                }
            } else {
                if (r0 < n) {
                    float* p = &g_sums[g0 * FDIM + col];
                    asm volatile("red.global.add.v2.f32 [%0], {%1,%2};"
                                 :: "l"(p), "f"(o0.x), "f"(o0.y) : "memory");
                }
                if (r1 < n) {
                    float* p = &g_sums[g1 * FDIM + col];
                    asm volatile("red.global.add.v2.f32 [%0], {%1,%2};"
                                 :: "l"(p), "f"(o1.x), "f"(o1.y) : "memory");
                }
            }
        }
    }
}

// ================= pooling counts + classifier =================
__global__ void cnt_kernel(const int* __restrict__ batch, int n) {
    int i = blockIdx.x * blockDim.x + threadIdx.x;
    if (i < n) atomicAdd(&g_cnt[batch[i]], 1.0f);
}
__global__ void final_kernel(const float* __restrict__ Wl, const float* __restrict__ bl,
                             float* __restrict__ out, int ngraphs) {
    int tid = blockIdx.x * blockDim.x + threadIdx.x;
    if (tid >= ngraphs * CLS) return;
    int g = tid / CLS;
    int c = tid % CLS;
    float s = 0.0f;
    const float* sp = &g_sums[g * FDIM];
#pragma unroll 16
    for (int d = 0; d < FDIM; ++d) s = fmaf(sp[d], Wl[d * CLS + c], s);
    float cnt = fmaxf(g_cnt[g], 1.0f);
    out[g * CLS + c] = s / cnt + bl[c];
}

// ---------------------------------------------------------------
extern "C" void kernel_launch(void* const* d_in, const int* in_sizes, int n_in,
                              void* d_out, int out_size) {
    const float* x   = (const float*)d_in[0];
    const int*   ei  = (const int*)  d_in[1];
    const int*   bat = (const int*)  d_in[2];
    const float* W1  = (const float*)d_in[3];
    const float* b1  = (const float*)d_in[4];
    const float* W2  = (const float*)d_in[5];
    const float* b2  = (const float*)d_in[6];
    const float* W3  = (const float*)d_in[7];
    const float* b3  = (const float*)d_in[8];
    const float* Wl  = (const float*)d_in[9];
    const float* bl  = (const float*)d_in[10];
    float* out = (float*)d_out;

    const int n = in_sizes[0] / FDIM;
    const int E = in_sizes[1] / 2;
    const int G = out_size / CLS;
    const int* src = ei;
    const int* dst = ei + E;
    const int ntiles = (n + 127) / 128;

    float *deg, *sums, *cnt;
    int *rcnt, *fill;
    uint32_t *X, *T1, *T2, *H1, *H2, *Wc;
    cudaGetSymbolAddress((void**)&deg,  g_deg);
    cudaGetSymbolAddress((void**)&rcnt, g_rcnt);
    cudaGetSymbolAddress((void**)&fill, g_fill);
    cudaGetSymbolAddress((void**)&X,  g_X);
    cudaGetSymbolAddress((void**)&T1, g_T1);
    cudaGetSymbolAddress((void**)&T2, g_T2);
    cudaGetSymbolAddress((void**)&H1, g_H1);
    cudaGetSymbolAddress((void**)&H2, g_H2);
    cudaGetSymbolAddress((void**)&sums, g_sums);
    cudaGetSymbolAddress((void**)&cnt,  g_cnt);
    cudaGetSymbolAddress((void**)&Wc,   g_Wc);

    cudaFuncSetAttribute(gemm_mma_kernel<0>, cudaFuncAttributeMaxDynamicSharedMemorySize, SM_GEMM);
    cudaFuncSetAttribute(gemm_mma_kernel<2>, cudaFuncAttributeMaxDynamicSharedMemorySize, SM_GEMM);

    const int TB = 256;

    cudaMemsetAsync(deg,  0, (size_t)n * sizeof(float));
    cudaMemsetAsync(rcnt, 0, (size_t)n * sizeof(int));
    cudaMemsetAsync(fill, 0, (size_t)n * sizeof(int));
    cudaMemsetAsync(sums, 0, (size_t)G * FDIM * sizeof(float));
    cudaMemsetAsync(cnt,  0, (size_t)G * sizeof(float));

    // prepass
    degcnt_kernel<<<(E + TB - 1) / TB, TB>>>(src, dst, E);
    const int nb = (n + SCAN_B - 1) / SCAN_B;
    scan1_kernel<<<nb, SCAN_B>>>(n);
    scan2_kernel<<<1, 256>>>(nb);
    scan3_kernel<<<(n + TB - 1) / TB, TB>>>(n);
    {
        int work = (E > n * 32) ? E : n * 32;
        fillx_kernel<<<(work + TB - 1) / TB, TB>>>(src, dst, E, (const float4*)x, n);
    }
    wcvt_kernel<<<(9 * 8192 + TB - 1) / TB, TB>>>(W1, W2, W3, Wc);
    cnt_kernel<<<(n + TB - 1) / TB, TB>>>(bat, n);

    const int propBlocks = (n * 32 + TB - 1) / TB;

    // layer 1
    prop_csr_kernel<0><<<propBlocks, TB>>>((const uint4*)X, nullptr, (uint4*)T1, n);
    prop_csr_kernel<1><<<propBlocks, TB>>>((const uint4*)T1, (const uint4*)X, (uint4*)T2, n);
    gemm_mma_kernel<0><<<ntiles, 256, SM_GEMM>>>(X, T1, T2, Wc, b1, H1, nullptr, n);
    // layer 2
    prop_csr_kernel<0><<<propBlocks, TB>>>((const uint4*)H1, nullptr, (uint4*)T1, n);
    prop_csr_kernel<1><<<propBlocks, TB>>>((const uint4*)T1, (const uint4*)H1, (uint4*)T2, n);
    gemm_mma_kernel<0><<<ntiles, 256, SM_GEMM>>>(H1, T1, T2, Wc + (size_t)3 * 16384, b2, H2, nullptr, n);
    // layer 3 (pool fused)
    prop_csr_kernel<0><<<propBlocks, TB>>>((const uint4*)H2, nullptr, (uint4*)T1, n);
    prop_csr_kernel<1><<<propBlocks, TB>>>((const uint4*)T1, (const uint4*)H2, (uint4*)T2, n);
    gemm_mma_kernel<2><<<ntiles, 256, SM_GEMM>>>(H2, T1, T2, Wc + (size_t)6 * 16384, b3, nullptr, bat, n);

    // classifier
    final_kernel<<<(G * CLS + TB - 1) / TB, TB>>>(Wl, bl, out, G);
}

// round 10
// speedup vs baseline: 1.2177x; 1.0986x over previous
#include <cuda_runtime.h>
#include <cuda_bf16.h>
#include <cstdint>

#define NMAX 100000
#define NPAD 100128
#define EMAX 1600000
#define FDIM 128
#define GMAX 64
#define CLS  10
#define SCAN_B 1024

// ---- scratch ----
__device__ float g_deg    [NMAX];
__device__ float g_dinv   [NMAX];
__device__ int   g_rcnt   [NMAX];
__device__ int   g_incl   [NMAX];
__device__ int   g_part   [256];
__device__ int   g_rowptr [NMAX + 1];
__device__ int   g_fill   [NMAX];
__device__ int   g_csrsrc [EMAX];
__device__ float g_csrw   [EMAX];
// combined bf16 hi/lo planes: row = 512B = 8 groups x [4 granules x (hi u2 | lo u2)]
__device__ uint32_t g_X [NPAD * 128];
__device__ uint32_t g_T1[NPAD * 128];
__device__ uint32_t g_Y [NPAD * 128];
__device__ uint32_t g_H1[NPAD * 128];
__device__ uint32_t g_H2[NPAD * 128];
__device__ float g_sums[GMAX * FDIM];
// combined weights: [layer][src(0:W0-W2, 1:W1, 2:2*W2)] 128 n-rows x 512B interleaved
__device__ uint32_t g_Wc[9 * 16384];

// byte offset (within a 512B row) of the u32 holding cols (c, c+1); lo plane at +8
__host__ __device__ __forceinline__ int posu32(int c) {
    int grp = c >> 4, pg = (c >> 1) & 7;
    return grp * 64 + (pg & 3) * 16 + (pg >> 2) * 4;
}

__device__ __forceinline__ float4 dec4(uint4 v) {
    float a0 = __uint_as_float(v.x << 16)          + __uint_as_float(v.z << 16);
    float a1 = __uint_as_float(v.x & 0xffff0000u)  + __uint_as_float(v.z & 0xffff0000u);
    float a2 = __uint_as_float(v.y << 16)          + __uint_as_float(v.w << 16);
    float a3 = __uint_as_float(v.y & 0xffff0000u)  + __uint_as_float(v.w & 0xffff0000u);
    return make_float4(a0, a1, a2, a3);
}
__device__ __forceinline__ void enc_pair(float2 v, uint32_t& h, uint32_t& l) {
    __nv_bfloat16 h0 = __float2bfloat16(v.x), h1 = __float2bfloat16(v.y);
    float l0 = v.x - __bfloat162float(h0), l1 = v.y - __bfloat162float(h1);
    union { __nv_bfloat162 b; uint32_t u; } t;
    t.b = __halves2bfloat162(h0, h1); h = t.u;
    t.b = __halves2bfloat162(__float2bfloat16(l0), __float2bfloat16(l1)); l = t.u;
}
__device__ __forceinline__ uint4 enc4(float4 f) {
    uint4 o;
    enc_pair(make_float2(f.x, f.y), o.x, o.z);
    enc_pair(make_float2(f.z, f.w), o.y, o.w);
    return o;
}

// ================= prepass =================
__global__ void degcnt_kernel(const int* __restrict__ src, const int* __restrict__ dst, int E) {
    int e = blockIdx.x * blockDim.x + threadIdx.x;
    if (e < E) {
        atomicAdd(&g_deg[src[e]], 1.0f);
        atomicAdd(&g_rcnt[dst[e]], 1);
    }
}
__global__ void scan1_kernel(int n) {
    __shared__ int sm[SCAN_B];
    int i = blockIdx.x * SCAN_B + threadIdx.x;
    int v = (i < n) ? g_rcnt[i] : 0;
    sm[threadIdx.x] = v;
    __syncthreads();
    for (int off = 1; off < SCAN_B; off <<= 1) {
        int t = (threadIdx.x >= off) ? sm[threadIdx.x - off] : 0;
        __syncthreads();
        sm[threadIdx.x] += t;
        __syncthreads();
    }
    if (i < n) g_incl[i] = sm[threadIdx.x];
    if (threadIdx.x == SCAN_B - 1) g_part[blockIdx.x] = sm[threadIdx.x];
}
__global__ void scan2_kernel(int nb) {
    __shared__ int sm[256];
    int v = (threadIdx.x < nb) ? g_part[threadIdx.x] : 0;
    sm[threadIdx.x] = v;
    __syncthreads();
    for (int off = 1; off < 256; off <<= 1) {
        int t = (threadIdx.x >= off) ? sm[threadIdx.x - off] : 0;
        __syncthreads();
        sm[threadIdx.x] += t;
        __syncthreads();
    }
    if (threadIdx.x < nb) g_part[threadIdx.x] = sm[threadIdx.x] - v;
}
__global__ void scan3_kernel(int n) {   // rowptr + dinv
    int i = blockIdx.x * blockDim.x + threadIdx.x;
    if (i < n) {
        g_rowptr[i + 1] = g_incl[i] + g_part[i / SCAN_B];
        float d = g_deg[i];
        g_dinv[i] = (d > 0.0f) ? rsqrtf(d) : 0.0f;
    }
    if (i == 0) g_rowptr[0] = 0;
}
// CSR fill + X -> interleaved planes
__global__ void fillx_kernel(const int* __restrict__ src, const int* __restrict__ dst, int E,
                             const float4* __restrict__ X, int n) {
    int idx = blockIdx.x * blockDim.x + threadIdx.x;
    if (idx < E) {
        int d = dst[idx], s = src[idx];
        int p = g_rowptr[d] + atomicAdd(&g_fill[d], 1);
        g_csrsrc[p] = s;
        g_csrw[p]   = -g_dinv[s] * g_dinv[d];
    }
    if (idx < n * 32) {
        int row = idx >> 5;
        int c4  = (idx & 31) << 2;
        float4 v = __ldg(&X[idx]);
        uint32_t h0, l0, h1, l1;
        enc_pair(make_float2(v.x, v.y), h0, l0);
        enc_pair(make_float2(v.z, v.w), h1, l1);
        char* xr = (char*)g_X + (size_t)row * 512;
        int p0 = posu32(c4), p1 = posu32(c4 + 2);
        *(uint32_t*)(xr + p0)     = h0;
        *(uint32_t*)(xr + p0 + 8) = l0;
        *(uint32_t*)(xr + p1)     = h1;
        *(uint32_t*)(xr + p1 + 8) = l1;
    }
}

// ================= CSR propagation: one warp per row, LDG.128 gathers ============
__global__ void __launch_bounds__(256) prop_csr_kernel(
    const uint4* __restrict__ X, uint4* __restrict__ O, int n) {
    int gw = (blockIdx.x * blockDim.x + threadIdx.x) >> 5;
    if (gw >= n) return;
    int lane = threadIdx.x & 31;
    int p    = __ldg(&g_rowptr[gw]);
    int end  = __ldg(&g_rowptr[gw + 1]);
    float4 acc = make_float4(0.f, 0.f, 0.f, 0.f);
    for (; p + 3 < end; p += 4) {
        int   s0 = __ldg(&g_csrsrc[p]),   s1 = __ldg(&g_csrsrc[p+1]);
        int   s2 = __ldg(&g_csrsrc[p+2]), s3 = __ldg(&g_csrsrc[p+3]);
        float w0 = __ldg(&g_csrw[p]),     w1 = __ldg(&g_csrw[p+1]);
        float w2 = __ldg(&g_csrw[p+2]),   w3 = __ldg(&g_csrw[p+3]);
        float4 v0 = dec4(__ldg(&X[(size_t)s0 * 32 + lane]));
        float4 v1 = dec4(__ldg(&X[(size_t)s1 * 32 + lane]));
        float4 v2 = dec4(__ldg(&X[(size_t)s2 * 32 + lane]));
        float4 v3 = dec4(__ldg(&X[(size_t)s3 * 32 + lane]));
        acc.x += w0*v0.x + w1*v1.x + w2*v2.x + w3*v3.x;
        acc.y += w0*v0.y + w1*v1.y + w2*v2.y + w3*v3.y;
        acc.z += w0*v0.z + w1*v1.z + w2*v2.z + w3*v3.z;
        acc.w += w0*v0.w + w1*v1.w + w2*v2.w + w3*v3.w;
    }
    for (; p < end; ++p) {
        int   s = __ldg(&g_csrsrc[p]);
        float w = __ldg(&g_csrw[p]);
        float4 v = dec4(__ldg(&X[(size_t)s * 32 + lane]));
        acc.x += w*v.x; acc.y += w*v.y; acc.z += w*v.z; acc.w += w*v.w;
    }
    O[(size_t)gw * 32 + lane] = enc4(acc);
}

// ================= weight pre-conversion (combined Chebyshev weights) ============
// src 0: W0 - W2, src 1: W1, src 2: 2*W2  (out = X(W0-W2) + T1*W1 + (L T1)(2W2))
__global__ void wcvt_kernel(const float* __restrict__ W1, const float* __restrict__ W2,
                            const float* __restrict__ W3, uint32_t* __restrict__ out) {
    int e = blockIdx.x * blockDim.x + threadIdx.x;
    if (e >= 9 * 8192) return;
    int L  = e / 24576;
    int r  = e % 24576;
    int s  = r >> 13;
    int rr = r & 8191;
    int p  = rr >> 7;
    int nn = rr & 127;
    const float* W = (L == 0) ? W1 : (L == 1) ? W2 : W3;
    int k = 2 * p;
    float v0, v1;
    if (s == 0) {
        v0 = W[k * 128 + nn]       - W[2 * 16384 + k * 128 + nn];
        v1 = W[(k + 1) * 128 + nn] - W[2 * 16384 + (k + 1) * 128 + nn];
    } else if (s == 1) {
        v0 = W[16384 + k * 128 + nn];
        v1 = W[16384 + (k + 1) * 128 + nn];
    } else {
        v0 = 2.0f * W[2 * 16384 + k * 128 + nn];
        v1 = 2.0f * W[2 * 16384 + (k + 1) * 128 + nn];
    }
    uint32_t h, l;
    enc_pair(make_float2(v0, v1), h, l);
    char* o = (char*)out + ((size_t)(L * 3 + s) * 128 + nn) * 512;
    int pos = posu32(k);
    *(uint32_t*)(o + pos)     = h;
    *(uint32_t*)(o + pos + 8) = l;
}

// ================= pipelined bf16 mma.sync GEMM =================
// BM=BN=128, 8 warps (4M x 2N). 6 chunks = 3 sources x 2 k-halves, 2-deep cp.async pipe.
#define HP 320                       // half-tile smem pitch (bank-conflict-free)
#define SM_GEMM (4 * 128 * HP)       // 163840: A0,A1,W0,W1 buffers

__device__ __forceinline__ uint32_t smem_u32(const void* p) {
    uint32_t a;
    asm("{ .reg .u64 t; cvta.to.shared.u64 t, %1; cvt.u32.u64 %0, t; }" : "=r"(a) : "l"(p));
    return a;
}
__device__ __forceinline__ void mma_bf16(float& d0, float& d1, float& d2, float& d3,
                                         uint32_t a0, uint32_t a1, uint32_t a2, uint32_t a3,
                                         uint32_t b0, uint32_t b1) {
    asm volatile("mma.sync.aligned.m16n8k16.row.col.f32.bf16.bf16.f32 "
                 "{%0,%1,%2,%3}, {%4,%5,%6,%7}, {%8,%9}, {%0,%1,%2,%3};"
                 : "+f"(d0), "+f"(d1), "+f"(d2), "+f"(d3)
                 : "r"(a0), "r"(a1), "r"(a2), "r"(a3), "r"(b0), "r"(b1));
}

template <int MODE>
__global__ void __launch_bounds__(256, 1) gemm_mma_kernel(
    const uint32_t* __restrict__ A0, const uint32_t* __restrict__ A1,
    const uint32_t* __restrict__ A2,
    const uint32_t* __restrict__ Wc, const float* __restrict__ bias,
    uint32_t* __restrict__ OUT, const int* __restrict__ batch, int n)
{
    extern __shared__ __align__(16) char smem[];
    const int tid  = threadIdx.x;
    const int wid  = tid >> 5;
    const int lane = tid & 31;
    const int wm   = wid & 3;
    const int wn   = wid >> 2;
    const int row0 = blockIdx.x * 128;

    float acc[2][8][4];
#pragma unroll
    for (int i = 0; i < 2; ++i)
#pragma unroll
        for (int j = 0; j < 8; ++j)
#pragma unroll
            for (int c = 0; c < 4; ++c) acc[i][j][c] = 0.0f;

    const uint32_t smA[2] = { smem_u32(smem),                smem_u32(smem + 128 * HP) };
    const uint32_t smW[2] = { smem_u32(smem + 2 * 128 * HP), smem_u32(smem + 3 * 128 * HP) };
    const uint32_t* Asrc[3] = { A0, A1, A2 };

    // stage chunk c (source s=c/2, half h=c&1) into buffers [c&1]
    auto stage = [&](int c) {
        int s = c >> 1, h = c & 1;
        const char* asrc = (const char*)Asrc[s] + (size_t)row0 * 512 + h * 256;
        const char* wsrc = (const char*)Wc + (size_t)s * 65536 + h * 256;
        uint32_t dA = smA[c & 1], dW = smW[c & 1];
#pragma unroll
        for (int i = 0; i < 8; ++i) {
            int q = i * 256 + tid;
            int r = q >> 4, g = q & 15;
            uint32_t od = (uint32_t)(r * HP + g * 16);
            size_t  so = (size_t)r * 512 + g * 16;
            asm volatile("cp.async.cg.shared.global [%0], [%1], 16;" :: "r"(dA + od), "l"(asrc + so));
            asm volatile("cp.async.cg.shared.global [%0], [%1], 16;" :: "r"(dW + od), "l"(wsrc + so));
        }
        asm volatile("cp.async.commit_group;" ::: "memory");
    };

    stage(0);
    stage(1);

#pragma unroll
    for (int c = 0; c < 6; ++c) {
        if (c < 5) asm volatile("cp.async.wait_group 1;" ::: "memory");
        else       asm volatile("cp.async.wait_group 0;" ::: "memory");
        __syncthreads();
        {
            const char* a0 = smem + (size_t)(c & 1) * 128 * HP
                           + (wm * 32 + (lane >> 2)) * HP + (lane & 3) * 16;
            const char* b0 = smem + (size_t)(2 + (c & 1)) * 128 * HP
                           + (wn * 64 + (lane >> 2)) * HP + (lane & 3) * 16;
#pragma unroll
            for (int g = 0; g < 4; ++g) {
                const int go = g * 64;
                uint4 va[4], vb[8];
#pragma unroll
                for (int r = 0; r < 4; ++r)
                    va[r] = *(const uint4*)(a0 + r * 8 * HP + go);
#pragma unroll
                for (int j = 0; j < 8; ++j)
                    vb[j] = *(const uint4*)(b0 + j * 8 * HP + go);
#pragma unroll
                for (int j = 0; j < 8; ++j) {
                    mma_bf16(acc[0][j][0], acc[0][j][1], acc[0][j][2], acc[0][j][3],
                             va[0].x, va[1].x, va[0].y, va[1].y, vb[j].x, vb[j].y);
                    mma_bf16(acc[1][j][0], acc[1][j][1], acc[1][j][2], acc[1][j][3],
                             va[2].x, va[3].x, va[2].y, va[3].y, vb[j].x, vb[j].y);
                    mma_bf16(acc[0][j][0], acc[0][j][1], acc[0][j][2], acc[0][j][3],
                             va[0].z, va[1].z, va[0].w, va[1].w, vb[j].x, vb[j].y);
                    mma_bf16(acc[1][j][0], acc[1][j][1], acc[1][j][2], acc[1][j][3],
                             va[2].z, va[3].z, va[2].w, va[3].w, vb[j].x, vb[j].y);
                    mma_bf16(acc[0][j][0], acc[0][j][1], acc[0][j][2], acc[0][j][3],
                             va[0].x, va[1].x, va[0].y, va[1].y, vb[j].z, vb[j].w);
                    mma_bf16(acc[1][j][0], acc[1][j][1], acc[1][j][2], acc[1][j][3],
                             va[2].x, va[3].x, va[2].y, va[3].y, vb[j].z, vb[j].w);
                }
            }
        }
        __syncthreads();
        if (c + 2 < 6) stage(c + 2);
    }

    // ---- epilogue ----
#pragma unroll
    for (int i = 0; i < 2; ++i) {
        int r0 = row0 + wm * 32 + i * 16 + (lane >> 2);
        int r1 = r0 + 8;
        int g0 = 0, g1 = 0;
        if (MODE == 2) {
            if (r0 < n) g0 = __ldg(&batch[r0]);
            if (r1 < n) g1 = __ldg(&batch[r1]);
        }
#pragma unroll
        for (int j = 0; j < 8; ++j) {
            int col = wn * 64 + j * 8 + (lane & 3) * 2;
            float2 bv = __ldg((const float2*)&bias[col]);
            float2 o0 = make_float2(acc[i][j][0] + bv.x, acc[i][j][1] + bv.y);
            float2 o1 = make_float2(acc[i][j][2] + bv.x, acc[i][j][3] + bv.y);
            if (MODE == 0) {
                o0.x = fmaxf(o0.x, 0.f); o0.y = fmaxf(o0.y, 0.f);
                o1.x = fmaxf(o1.x, 0.f); o1.y = fmaxf(o1.y, 0.f);
                int pos = posu32(col);
                uint32_t h, l;
                if (r0 < n) {
                    enc_pair(o0, h, l);
                    char* orow = (char*)OUT + (size_t)r0 * 512;
                    *(uint32_t*)(orow + pos)     = h;
                    *(uint32_t*)(orow + pos + 8) = l;
                }
                if (r1 < n) {
                    enc_pair(o1, h, l);
                    char* orow = (char*)OUT + (size_t)r1 * 512;
                    *(uint32_t*)(orow + pos)     = h;
                    *(uint32_t*)(orow + pos + 8) = l;
                }
            } else {
                if (r0 < n) {
                    float* p = &g_sums[g0 * FDIM + col];
                    asm volatile("red.global.add.v2.f32 [%0], {%1,%2};"
                                 :: "l"(p), "f"(o0.x), "f"(o0.y) : "memory");
                }
                if (r1 < n) {
                    float* p = &g_sums[g1 * FDIM + col];
                    asm volatile("red.global.add.v2.f32 [%0], {%1,%2};"
                                 :: "l"(p), "f"(o1.x), "f"(o1.y) : "memory");
                }
            }
        }
    }
}

// ================= classifier (counts via binary search; batch is sorted) ========
__global__ void final_kernel(const int* __restrict__ batch, int n,
                             const float* __restrict__ Wl, const float* __restrict__ bl,
                             float* __restrict__ out, int ngraphs) {
    int tid = blockIdx.x * blockDim.x + threadIdx.x;
    if (tid >= ngraphs * CLS) return;
    int g = tid / CLS;
    int c = tid % CLS;
    int lo = 0, hi = n;
    while (lo < hi) { int m = (lo + hi) >> 1; if (__ldg(&batch[m]) < g) lo = m + 1; else hi = m; }
    int start = lo;
    lo = start; hi = n;
    while (lo < hi) { int m = (lo + hi) >> 1; if (__ldg(&batch[m]) < g + 1) lo = m + 1; else hi = m; }
    float cnt = (float)(lo - start);
    float s = 0.0f;
    const float* sp = &g_sums[g * FDIM];
#pragma unroll 16
    for (int d = 0; d < FDIM; ++d) s = fmaf(sp[d], Wl[d * CLS + c], s);
    out[g * CLS + c] = s / fmaxf(cnt, 1.0f) + bl[c];
}

// ---------------------------------------------------------------
extern "C" void kernel_launch(void* const* d_in, const int* in_sizes, int n_in,
                              void* d_out, int out_size) {
    const float* x   = (const float*)d_in[0];
    const int*   ei  = (const int*)  d_in[1];
    const int*   bat = (const int*)  d_in[2];
    const float* W1  = (const float*)d_in[3];
    const float* b1  = (const float*)d_in[4];
    const float* W2  = (const float*)d_in[5];
    const float* b2  = (const float*)d_in[6];
    const float* W3  = (const float*)d_in[7];
    const float* b3  = (const float*)d_in[8];
    const float* Wl  = (const float*)d_in[9];
    const float* bl  = (const float*)d_in[10];
    float* out = (float*)d_out;

    const int n = in_sizes[0] / FDIM;
    const int E = in_sizes[1] / 2;
    const int G = out_size / CLS;
    const int* src = ei;
    const int* dst = ei + E;
    const int ntiles = (n + 127) / 128;

    float *deg, *sums;
    int *rcnt, *fill;
    uint32_t *X, *T1, *Y, *H1, *H2, *Wc;
    cudaGetSymbolAddress((void**)&deg,  g_deg);
    cudaGetSymbolAddress((void**)&rcnt, g_rcnt);
    cudaGetSymbolAddress((void**)&fill, g_fill);
    cudaGetSymbolAddress((void**)&X,  g_X);
    cudaGetSymbolAddress((void**)&T1, g_T1);
    cudaGetSymbolAddress((void**)&Y,  g_Y);
    cudaGetSymbolAddress((void**)&H1, g_H1);
    cudaGetSymbolAddress((void**)&H2, g_H2);
    cudaGetSymbolAddress((void**)&sums, g_sums);
    cudaGetSymbolAddress((void**)&Wc,   g_Wc);

    cudaFuncSetAttribute(gemm_mma_kernel<0>, cudaFuncAttributeMaxDynamicSharedMemorySize, SM_GEMM);
    cudaFuncSetAttribute(gemm_mma_kernel<2>, cudaFuncAttributeMaxDynamicSharedMemorySize, SM_GEMM);

    const int TB = 256;

    cudaMemsetAsync(deg,  0, (size_t)n * sizeof(float));
    cudaMemsetAsync(rcnt, 0, (size_t)n * sizeof(int));
    cudaMemsetAsync(fill, 0, (size_t)n * sizeof(int));
    cudaMemsetAsync(sums, 0, (size_t)G * FDIM * sizeof(float));

    // prepass
    degcnt_kernel<<<(E + TB - 1) / TB, TB>>>(src, dst, E);
    const int nb = (n + SCAN_B - 1) / SCAN_B;
    scan1_kernel<<<nb, SCAN_B>>>(n);
    scan2_kernel<<<1, 256>>>(nb);
    scan3_kernel<<<(n + TB - 1) / TB, TB>>>(n);
    {
        int work = (E > n * 32) ? E : n * 32;
        fillx_kernel<<<(work + TB - 1) / TB, TB>>>(src, dst, E, (const float4*)x, n);
    }
    wcvt_kernel<<<(9 * 8192 + TB - 1) / TB, TB>>>(W1, W2, W3, Wc);

    const int propBlocks = (n * 32 + TB - 1) / TB;

    // layer 1
    prop_csr_kernel<<<propBlocks, TB>>>((const uint4*)X, (uint4*)T1, n);
    prop_csr_kernel<<<propBlocks, TB>>>((const uint4*)T1, (uint4*)Y, n);
    gemm_mma_kernel<0><<<ntiles, 256, SM_GEMM>>>(X, T1, Y, Wc, b1, H1, nullptr, n);
    // layer 2
    prop_csr_kernel<<<propBlocks, TB>>>((const uint4*)H1, (uint4*)T1, n);
    prop_csr_kernel<<<propBlocks, TB>>>((const uint4*)T1, (uint4*)Y, n);
    gemm_mma_kernel<0><<<ntiles, 256, SM_GEMM>>>(H1, T1, Y, Wc + (size_t)3 * 16384, b2, H2, nullptr, n);
    // layer 3 (pool fused)
    prop_csr_kernel<<<propBlocks, TB>>>((const uint4*)H2, (uint4*)T1, n);
    prop_csr_kernel<<<propBlocks, TB>>>((const uint4*)T1, (uint4*)Y, n);
    gemm_mma_kernel<2><<<ntiles, 256, SM_GEMM>>>(H2, T1, Y, Wc + (size_t)6 * 16384, b3, nullptr, bat, n);

    // classifier
    final_kernel<<<(G * CLS + TB - 1) / TB, TB>>>(bat, n, Wl, bl, out, G);
}

// round 11
// speedup vs baseline: 1.2421x; 1.0200x over previous
#include <cuda_runtime.h>
#include <cuda_bf16.h>
#include <cstdint>

#define NMAX 100000
#define NPAD 100128
#define EMAX 1600000
#define FDIM 128
#define GMAX 64
#define CLS  10
#define SCAN_B 1024

// ---- scratch ----
__device__ float g_deg    [NMAX];
__device__ float g_dinv   [NMAX];
__device__ int   g_rcnt   [NMAX];
__device__ int   g_incl   [NMAX];
__device__ int   g_part   [256];
__device__ int   g_rowptr [NMAX + 1];
__device__ int   g_fill   [NMAX];
__device__ int   g_csrsrc [EMAX];
__device__ float g_csrw   [EMAX];
// combined bf16 hi/lo planes: row = 512B = 8 groups x [4 granules x (hi u2 | lo u2)]
__device__ uint32_t g_X [NPAD * 128];
__device__ uint32_t g_T1[NPAD * 128];
__device__ uint32_t g_Y [NPAD * 128];
__device__ uint32_t g_H1[NPAD * 128];
__device__ uint32_t g_H2[NPAD * 128];
__device__ float g_sums[GMAX * FDIM];
// combined weights: [layer][src(0:W0-W2, 1:W1, 2:2*W2)] 128 n-rows x 512B interleaved
__device__ uint32_t g_Wc[9 * 16384];

// byte offset (within a 512B row) of the u32 holding cols (c, c+1); lo plane at +8
__host__ __device__ __forceinline__ int posu32(int c) {
    int grp = c >> 4, pg = (c >> 1) & 7;
    return grp * 64 + (pg & 3) * 16 + (pg >> 2) * 4;
}

__device__ __forceinline__ float4 dec4(uint4 v) {
    float a0 = __uint_as_float(v.x << 16)          + __uint_as_float(v.z << 16);
    float a1 = __uint_as_float(v.x & 0xffff0000u)  + __uint_as_float(v.z & 0xffff0000u);
    float a2 = __uint_as_float(v.y << 16)          + __uint_as_float(v.w << 16);
    float a3 = __uint_as_float(v.y & 0xffff0000u)  + __uint_as_float(v.w & 0xffff0000u);
    return make_float4(a0, a1, a2, a3);
}
__device__ __forceinline__ void enc_pair(float2 v, uint32_t& h, uint32_t& l) {
    __nv_bfloat16 h0 = __float2bfloat16(v.x), h1 = __float2bfloat16(v.y);
    float l0 = v.x - __bfloat162float(h0), l1 = v.y - __bfloat162float(h1);
    union { __nv_bfloat162 b; uint32_t u; } t;
    t.b = __halves2bfloat162(h0, h1); h = t.u;
    t.b = __halves2bfloat162(__float2bfloat16(l0), __float2bfloat16(l1)); l = t.u;
}
__device__ __forceinline__ uint4 enc4(float4 f) {
    uint4 o;
    enc_pair(make_float2(f.x, f.y), o.x, o.z);
    enc_pair(make_float2(f.z, f.w), o.y, o.w);
    return o;
}

// ================= prepass =================
__global__ void degcnt_kernel(const int* __restrict__ src, const int* __restrict__ dst, int E) {
    int e = blockIdx.x * blockDim.x + threadIdx.x;
    if (e < E) {
        atomicAdd(&g_deg[src[e]], 1.0f);
        atomicAdd(&g_rcnt[dst[e]], 1);
    }
}
__global__ void scan1_kernel(int n) {
    __shared__ int sm[SCAN_B];
    int i = blockIdx.x * SCAN_B + threadIdx.x;
    int v = (i < n) ? g_rcnt[i] : 0;
    sm[threadIdx.x] = v;
    __syncthreads();
    for (int off = 1; off < SCAN_B; off <<= 1) {
        int t = (threadIdx.x >= off) ? sm[threadIdx.x - off] : 0;
        __syncthreads();
        sm[threadIdx.x] += t;
        __syncthreads();
    }
    if (i < n) g_incl[i] = sm[threadIdx.x];
    if (threadIdx.x == SCAN_B - 1) g_part[blockIdx.x] = sm[threadIdx.x];
}
__global__ void scan2_kernel(int nb) {
    __shared__ int sm[256];
    int v = (threadIdx.x < nb) ? g_part[threadIdx.x] : 0;
    sm[threadIdx.x] = v;
    __syncthreads();
    for (int off = 1; off < 256; off <<= 1) {
        int t = (threadIdx.x >= off) ? sm[threadIdx.x - off] : 0;
        __syncthreads();
        sm[threadIdx.x] += t;
        __syncthreads();
    }
    if (threadIdx.x < nb) g_part[threadIdx.x] = sm[threadIdx.x] - v;
}
__global__ void scan3_kernel(int n) {   // rowptr + dinv
    int i = blockIdx.x * blockDim.x + threadIdx.x;
    if (i < n) {
        g_rowptr[i + 1] = g_incl[i] + g_part[i / SCAN_B];
        float d = g_deg[i];
        g_dinv[i] = (d > 0.0f) ? rsqrtf(d) : 0.0f;
    }
    if (i == 0) g_rowptr[0] = 0;
}
// CSR fill + X -> interleaved planes
__global__ void fillx_kernel(const int* __restrict__ src, const int* __restrict__ dst, int E,
                             const float4* __restrict__ X, int n) {
    int idx = blockIdx.x * blockDim.x + threadIdx.x;
    if (idx < E) {
        int d = dst[idx], s = src[idx];
        int p = g_rowptr[d] + atomicAdd(&g_fill[d], 1);
        g_csrsrc[p] = s;
        g_csrw[p]   = -g_dinv[s] * g_dinv[d];
    }
    if (idx < n * 32) {
        int row = idx >> 5;
        int c4  = (idx & 31) << 2;
        float4 v = __ldg(&X[idx]);
        uint32_t h0, l0, h1, l1;
        enc_pair(make_float2(v.x, v.y), h0, l0);
        enc_pair(make_float2(v.z, v.w), h1, l1);
        char* xr = (char*)g_X + (size_t)row * 512;
        int p0 = posu32(c4), p1 = posu32(c4 + 2);
        *(uint32_t*)(xr + p0)     = h0;
        *(uint32_t*)(xr + p0 + 8) = l0;
        *(uint32_t*)(xr + p1)     = h1;
        *(uint32_t*)(xr + p1 + 8) = l1;
    }
}

// ================= CSR propagation: one warp per row, LDG.128 gathers ============
__global__ void __launch_bounds__(256) prop_csr_kernel(
    const uint4* __restrict__ X, uint4* __restrict__ O, int n) {
    int gw = (blockIdx.x * blockDim.x + threadIdx.x) >> 5;
    if (gw >= n) return;
    int lane = threadIdx.x & 31;
    int p    = __ldg(&g_rowptr[gw]);
    int end  = __ldg(&g_rowptr[gw + 1]);
    float4 acc = make_float4(0.f, 0.f, 0.f, 0.f);
    for (; p + 3 < end; p += 4) {
        int   s0 = __ldg(&g_csrsrc[p]),   s1 = __ldg(&g_csrsrc[p+1]);
        int   s2 = __ldg(&g_csrsrc[p+2]), s3 = __ldg(&g_csrsrc[p+3]);
        float w0 = __ldg(&g_csrw[p]),     w1 = __ldg(&g_csrw[p+1]);
        float w2 = __ldg(&g_csrw[p+2]),   w3 = __ldg(&g_csrw[p+3]);
        float4 v0 = dec4(__ldg(&X[(size_t)s0 * 32 + lane]));
        float4 v1 = dec4(__ldg(&X[(size_t)s1 * 32 + lane]));
        float4 v2 = dec4(__ldg(&X[(size_t)s2 * 32 + lane]));
        float4 v3 = dec4(__ldg(&X[(size_t)s3 * 32 + lane]));
        acc.x += w0*v0.x + w1*v1.x + w2*v2.x + w3*v3.x;
        acc.y += w0*v0.y + w1*v1.y + w2*v2.y + w3*v3.y;
        acc.z += w0*v0.z + w1*v1.z + w2*v2.z + w3*v3.z;
        acc.w += w0*v0.w + w1*v1.w + w2*v2.w + w3*v3.w;
    }
    for (; p < end; ++p) {
        int   s = __ldg(&g_csrsrc[p]);
        float w = __ldg(&g_csrw[p]);
        float4 v = dec4(__ldg(&X[(size_t)s * 32 + lane]));
        acc.x += w*v.x; acc.y += w*v.y; acc.z += w*v.z; acc.w += w*v.w;
    }
    O[(size_t)gw * 32 + lane] = enc4(acc);
}

// ================= weight pre-conversion (combined Chebyshev weights) ============
// src 0: W0 - W2, src 1: W1, src 2: 2*W2  (out = X(W0-W2) + T1*W1 + (L T1)(2W2))
__global__ void wcvt_kernel(const float* __restrict__ W1, const float* __restrict__ W2,
                            const float* __restrict__ W3, uint32_t* __restrict__ out) {
    int e = blockIdx.x * blockDim.x + threadIdx.x;
    if (e >= 9 * 8192) return;
    int L  = e / 24576;
    int r  = e % 24576;
    int s  = r >> 13;
    int rr = r & 8191;
    int p  = rr >> 7;
    int nn = rr & 127;
    const float* W = (L == 0) ? W1 : (L == 1) ? W2 : W3;
    int k = 2 * p;
    float v0, v1;
    if (s == 0) {
        v0 = W[k * 128 + nn]       - W[2 * 16384 + k * 128 + nn];
        v1 = W[(k + 1) * 128 + nn] - W[2 * 16384 + (k + 1) * 128 + nn];
    } else if (s == 1) {
        v0 = W[16384 + k * 128 + nn];
        v1 = W[16384 + (k + 1) * 128 + nn];
    } else {
        v0 = 2.0f * W[2 * 16384 + k * 128 + nn];
        v1 = 2.0f * W[2 * 16384 + (k + 1) * 128 + nn];
    }
    uint32_t h, l;
    enc_pair(make_float2(v0, v1), h, l);
    char* o = (char*)out + ((size_t)(L * 3 + s) * 128 + nn) * 512;
    int pos = posu32(k);
    *(uint32_t*)(o + pos)     = h;
    *(uint32_t*)(o + pos + 8) = l;
}

// ================= pipelined bf16 mma.sync GEMM =================
// BM=BN=128, 8 warps (4M x 2N). 6 chunks = 3 sources x 2 k-halves, 2-deep cp.async pipe.
#define HP 320                       // half-tile smem pitch (bank-conflict-free)
#define SM_GEMM (4 * 128 * HP)       // 163840: A0,A1,W0,W1 buffers

__device__ __forceinline__ uint32_t smem_u32(const void* p) {
    uint32_t a;
    asm("{ .reg .u64 t; cvta.to.shared.u64 t, %1; cvt.u32.u64 %0, t; }" : "=r"(a) : "l"(p));
    return a;
}
__device__ __forceinline__ void mma_bf16(float& d0, float& d1, float& d2, float& d3,
                                         uint32_t a0, uint32_t a1, uint32_t a2, uint32_t a3,
                                         uint32_t b0, uint32_t b1) {
    asm volatile("mma.sync.aligned.m16n8k16.row.col.f32.bf16.bf16.f32 "
                 "{%0,%1,%2,%3}, {%4,%5,%6,%7}, {%8,%9}, {%0,%1,%2,%3};"
                 : "+f"(d0), "+f"(d1), "+f"(d2), "+f"(d3)
                 : "r"(a0), "r"(a1), "r"(a2), "r"(a3), "r"(b0), "r"(b1));
}

template <int MODE>
__global__ void __launch_bounds__(256, 1) gemm_mma_kernel(
    const uint32_t* __restrict__ A0, const uint32_t* __restrict__ A1,
    const uint32_t* __restrict__ A2,
    const uint32_t* __restrict__ Wc, const float* __restrict__ bias,
    uint32_t* __restrict__ OUT, const int* __restrict__ batch, int n)
{
    extern __shared__ __align__(16) char smem[];
    const int tid  = threadIdx.x;
    const int wid  = tid >> 5;
    const int lane = tid & 31;
    const int wm   = wid & 3;
    const int wn   = wid >> 2;
    const int row0 = blockIdx.x * 128;

    float acc[2][8][4];
#pragma unroll
    for (int i = 0; i < 2; ++i)
#pragma unroll
        for (int j = 0; j < 8; ++j)
#pragma unroll
            for (int c = 0; c < 4; ++c) acc[i][j][c] = 0.0f;

    const uint32_t smA[2] = { smem_u32(smem),                smem_u32(smem + 128 * HP) };
    const uint32_t smW[2] = { smem_u32(smem + 2 * 128 * HP), smem_u32(smem + 3 * 128 * HP) };
    const uint32_t* Asrc[3] = { A0, A1, A2 };

    // stage chunk c (source s=c/2, half h=c&1) into buffers [c&1]
    auto stage = [&](int c) {
        int s = c >> 1, h = c & 1;
        const char* asrc = (const char*)Asrc[s] + (size_t)row0 * 512 + h * 256;
        const char* wsrc = (const char*)Wc + (size_t)s * 65536 + h * 256;
        uint32_t dA = smA[c & 1], dW = smW[c & 1];
#pragma unroll
        for (int i = 0; i < 8; ++i) {
            int q = i * 256 + tid;
            int r = q >> 4, g = q & 15;
            uint32_t od = (uint32_t)(r * HP + g * 16);
            size_t  so = (size_t)r * 512 + g * 16;
            asm volatile("cp.async.cg.shared.global [%0], [%1], 16;" :: "r"(dA + od), "l"(asrc + so));
            asm volatile("cp.async.cg.shared.global [%0], [%1], 16;" :: "r"(dW + od), "l"(wsrc + so));
        }
        asm volatile("cp.async.commit_group;" ::: "memory");
    };

    stage(0);
    stage(1);

#pragma unroll
    for (int c = 0; c < 6; ++c) {
        if (c < 5) asm volatile("cp.async.wait_group 1;" ::: "memory");
        else       asm volatile("cp.async.wait_group 0;" ::: "memory");
        __syncthreads();
        {
            const char* a0 = smem + (size_t)(c & 1) * 128 * HP
                           + (wm * 32 + (lane >> 2)) * HP + (lane & 3) * 16;
            const char* b0 = smem + (size_t)(2 + (c & 1)) * 128 * HP
                           + (wn * 64 + (lane >> 2)) * HP + (lane & 3) * 16;
#pragma unroll
            for (int g = 0; g < 4; ++g) {
                const int go = g * 64;
                uint4 va[4], vb[8];
#pragma unroll
                for (int r = 0; r < 4; ++r)
                    va[r] = *(const uint4*)(a0 + r * 8 * HP + go);
#pragma unroll
                for (int j = 0; j < 8; ++j)
                    vb[j] = *(const uint4*)(b0 + j * 8 * HP + go);
#pragma unroll
                for (int j = 0; j < 8; ++j) {
                    mma_bf16(acc[0][j][0], acc[0][j][1], acc[0][j][2], acc[0][j][3],
                             va[0].x, va[1].x, va[0].y, va[1].y, vb[j].x, vb[j].y);
                    mma_bf16(acc[1][j][0], acc[1][j][1], acc[1][j][2], acc[1][j][3],
                             va[2].x, va[3].x, va[2].y, va[3].y, vb[j].x, vb[j].y);
                    mma_bf16(acc[0][j][0], acc[0][j][1], acc[0][j][2], acc[0][j][3],
                             va[0].z, va[1].z, va[0].w, va[1].w, vb[j].x, vb[j].y);
                    mma_bf16(acc[1][j][0], acc[1][j][1], acc[1][j][2], acc[1][j][3],
                             va[2].z, va[3].z, va[2].w, va[3].w, vb[j].x, vb[j].y);
                    mma_bf16(acc[0][j][0], acc[0][j][1], acc[0][j][2], acc[0][j][3],
                             va[0].x, va[1].x, va[0].y, va[1].y, vb[j].z, vb[j].w);
                    mma_bf16(acc[1][j][0], acc[1][j][1], acc[1][j][2], acc[1][j][3],
                             va[2].x, va[3].x, va[2].y, va[3].y, vb[j].z, vb[j].w);
                }
            }
        }
        __syncthreads();
        if (c + 2 < 6) stage(c + 2);
    }

    // ---- epilogue ----
#pragma unroll
    for (int i = 0; i < 2; ++i) {
        int r0 = row0 + wm * 32 + i * 16 + (lane >> 2);
        int r1 = r0 + 8;
        int g0 = 0, g1 = 0;
        if (MODE == 2) {
            if (r0 < n) g0 = __ldg(&batch[r0]);
            if (r1 < n) g1 = __ldg(&batch[r1]);
        }
#pragma unroll
        for (int j = 0; j < 8; ++j) {
            int col = wn * 64 + j * 8 + (lane & 3) * 2;
            float2 bv = __ldg((const float2*)&bias[col]);
            float2 o0 = make_float2(acc[i][j][0] + bv.x, acc[i][j][1] + bv.y);
            float2 o1 = make_float2(acc[i][j][2] + bv.x, acc[i][j][3] + bv.y);
            if (MODE == 0) {
                o0.x = fmaxf(o0.x, 0.f); o0.y = fmaxf(o0.y, 0.f);
                o1.x = fmaxf(o1.x, 0.f); o1.y = fmaxf(o1.y, 0.f);
                int pos = posu32(col);
                uint32_t h, l;
                if (r0 < n) {
                    enc_pair(o0, h, l);
                    char* orow = (char*)OUT + (size_t)r0 * 512;
                    *(uint32_t*)(orow + pos)     = h;
                    *(uint32_t*)(orow + pos + 8) = l;
                }
                if (r1 < n) {
                    enc_pair(o1, h, l);
                    char* orow = (char*)OUT + (size_t)r1 * 512;
                    *(uint32_t*)(orow + pos)     = h;
                    *(uint32_t*)(orow + pos + 8) = l;
                }
            } else {
                if (r0 < n) {
                    float* p = &g_sums[g0 * FDIM + col];
                    asm volatile("red.global.add.v2.f32 [%0], {%1,%2};"
                                 :: "l"(p), "f"(o0.x), "f"(o0.y) : "memory");
                }
                if (r1 < n) {
                    float* p = &g_sums[g1 * FDIM + col];
                    asm volatile("red.global.add.v2.f32 [%0], {%1,%2};"
                                 :: "l"(p), "f"(o1.x), "f"(o1.y) : "memory");
                }
            }
        }
    }
}

// ================= classifier (counts via binary search; batch is sorted) ========
__global__ void final_kernel(const int* __restrict__ batch, int n,
                             const float* __restrict__ Wl, const float* __restrict__ bl,
                             float* __restrict__ out, int ngraphs) {
    int tid = blockIdx.x * blockDim.x + threadIdx.x;
    if (tid >= ngraphs * CLS) return;
    int g = tid / CLS;
    int c = tid % CLS;
    int lo = 0, hi = n;
    while (lo < hi) { int m = (lo + hi) >> 1; if (__ldg(&batch[m]) < g) lo = m + 1; else hi = m; }
    int start = lo;
    lo = start; hi = n;
    while (lo < hi) { int m = (lo + hi) >> 1; if (__ldg(&batch[m]) < g + 1) lo = m + 1; else hi = m; }
    float cnt = (float)(lo - start);
    float s = 0.0f;
    const float* sp = &g_sums[g * FDIM];
#pragma unroll 16
    for (int d = 0; d < FDIM; ++d) s = fmaf(sp[d], Wl[d * CLS + c], s);
    out[g * CLS + c] = s / fmaxf(cnt, 1.0f) + bl[c];
}

// ---------------------------------------------------------------
extern "C" void kernel_launch(void* const* d_in, const int* in_sizes, int n_in,
                              void* d_out, int out_size) {
    const float* x   = (const float*)d_in[0];
    const int*   ei  = (const int*)  d_in[1];
    const int*   bat = (const int*)  d_in[2];
    const float* W1  = (const float*)d_in[3];
    const float* b1  = (const float*)d_in[4];
    const float* W2  = (const float*)d_in[5];
    const float* b2  = (const float*)d_in[6];
    const float* W3  = (const float*)d_in[7];
    const float* b3  = (const float*)d_in[8];
    const float* Wl  = (const float*)d_in[9];
    const float* bl  = (const float*)d_in[10];
    float* out = (float*)d_out;

    const int n = in_sizes[0] / FDIM;
    const int E = in_sizes[1] / 2;
    const int G = out_size / CLS;
    const int* src = ei;
    const int* dst = ei + E;
    const int ntiles = (n + 127) / 128;

    float *deg, *sums;
    int *rcnt, *fill;
    uint32_t *X, *T1, *Y, *H1, *H2, *Wc;
    cudaGetSymbolAddress((void**)&deg,  g_deg);
    cudaGetSymbolAddress((void**)&rcnt, g_rcnt);
    cudaGetSymbolAddress((void**)&fill, g_fill);
    cudaGetSymbolAddress((void**)&X,  g_X);
    cudaGetSymbolAddress((void**)&T1, g_T1);
    cudaGetSymbolAddress((void**)&Y,  g_Y);
    cudaGetSymbolAddress((void**)&H1, g_H1);
    cudaGetSymbolAddress((void**)&H2, g_H2);
    cudaGetSymbolAddress((void**)&sums, g_sums);
    cudaGetSymbolAddress((void**)&Wc,   g_Wc);

    cudaFuncSetAttribute(gemm_mma_kernel<0>, cudaFuncAttributeMaxDynamicSharedMemorySize, SM_GEMM);
    cudaFuncSetAttribute(gemm_mma_kernel<2>, cudaFuncAttributeMaxDynamicSharedMemorySize, SM_GEMM);

    const int TB = 256;

    cudaMemsetAsync(deg,  0, (size_t)n * sizeof(float));
    cudaMemsetAsync(rcnt, 0, (size_t)n * sizeof(int));
    cudaMemsetAsync(fill, 0, (size_t)n * sizeof(int));
    cudaMemsetAsync(sums, 0, (size_t)G * FDIM * sizeof(float));

    // prepass
    degcnt_kernel<<<(E + TB - 1) / TB, TB>>>(src, dst, E);
    const int nb = (n + SCAN_B - 1) / SCAN_B;
    scan1_kernel<<<nb, SCAN_B>>>(n);
    scan2_kernel<<<1, 256>>>(nb);
    scan3_kernel<<<(n + TB - 1) / TB, TB>>>(n);
    {
        int work = (E > n * 32) ? E : n * 32;
        fillx_kernel<<<(work + TB - 1) / TB, TB>>>(src, dst, E, (const float4*)x, n);
    }
    wcvt_kernel<<<(9 * 8192 + TB - 1) / TB, TB>>>(W1, W2, W3, Wc);

    const int propBlocks = (n * 32 + TB - 1) / TB;

    // layer 1
    prop_csr_kernel<<<propBlocks, TB>>>((const uint4*)X, (uint4*)T1, n);
    prop_csr_kernel<<<propBlocks, TB>>>((const uint4*)T1, (uint4*)Y, n);
    gemm_mma_kernel<0><<<ntiles, 256, SM_GEMM>>>(X, T1, Y, Wc, b1, H1, nullptr, n);
    // layer 2
    prop_csr_kernel<<<propBlocks, TB>>>((const uint4*)H1, (uint4*)T1, n);
    prop_csr_kernel<<<propBlocks, TB>>>((const uint4*)T1, (uint4*)Y, n);
    gemm_mma_kernel<0><<<ntiles, 256, SM_GEMM>>>(H1, T1, Y, Wc + (size_t)3 * 16384, b2, H2, nullptr, n);
    // layer 3 (pool fused)
    prop_csr_kernel<<<propBlocks, TB>>>((const uint4*)H2, (uint4*)T1, n);
    prop_csr_kernel<<<propBlocks, TB>>>((const uint4*)T1, (uint4*)Y, n);
    gemm_mma_kernel<2><<<ntiles, 256, SM_GEMM>>>(H2, T1, Y, Wc + (size_t)6 * 16384, b3, nullptr, bat, n);

    // classifier
    final_kernel<<<(G * CLS + TB - 1) / TB, TB>>>(bat, n, Wl, bl, out, G);
}

// round 12
// speedup vs baseline: 1.2915x; 1.0398x over previous
#include <cuda_runtime.h>
#include <cuda_bf16.h>
#include <cstdint>

#define NMAX 100000
#define NPAD 100128
#define EMAX 1600000
#define FDIM 128
#define GMAX 64
#define CLS  10
#define SCAN_B 1024

// ---- scratch ----
__device__ float g_deg    [NMAX];
__device__ float g_dinv   [NMAX];
__device__ int   g_rcnt   [NMAX];
__device__ int   g_incl   [NMAX];
__device__ int   g_part   [256];
__device__ int   g_rowptr [NMAX + 1];
__device__ int   g_fill   [NMAX];
__device__ int2  g_csrent [EMAX];      // (src, w-as-int)
// combined bf16 hi/lo planes: row = 512B
__device__ uint32_t g_X [NPAD * 128];
__device__ uint32_t g_T1[NPAD * 128];
__device__ uint32_t g_Y [NPAD * 128];
__device__ uint32_t g_H1[NPAD * 128];
__device__ uint32_t g_H2[NPAD * 128];
__device__ float g_sums[GMAX * FDIM];
// combined weights: [layer][src(0:W0-W2, 1:W1, 2:2*W2)] 128 n-rows x 512B interleaved
__device__ uint32_t g_Wc[9 * 16384];

__host__ __device__ __forceinline__ int posu32(int c) {
    int grp = c >> 4, pg = (c >> 1) & 7;
    return grp * 64 + (pg & 3) * 16 + (pg >> 2) * 4;
}
__device__ __forceinline__ float4 dec4(uint4 v) {
    float a0 = __uint_as_float(v.x << 16)          + __uint_as_float(v.z << 16);
    float a1 = __uint_as_float(v.x & 0xffff0000u)  + __uint_as_float(v.z & 0xffff0000u);
    float a2 = __uint_as_float(v.y << 16)          + __uint_as_float(v.w << 16);
    float a3 = __uint_as_float(v.y & 0xffff0000u)  + __uint_as_float(v.w & 0xffff0000u);
    return make_float4(a0, a1, a2, a3);
}
__device__ __forceinline__ void enc_pair(float2 v, uint32_t& h, uint32_t& l) {
    __nv_bfloat16 h0 = __float2bfloat16(v.x), h1 = __float2bfloat16(v.y);
    float l0 = v.x - __bfloat162float(h0), l1 = v.y - __bfloat162float(h1);
    union { __nv_bfloat162 b; uint32_t u; } t;
    t.b = __halves2bfloat162(h0, h1); h = t.u;
    t.b = __halves2bfloat162(__float2bfloat16(l0), __float2bfloat16(l1)); l = t.u;
}
__device__ __forceinline__ uint4 enc4(float4 f) {
    uint4 o;
    enc_pair(make_float2(f.x, f.y), o.x, o.z);
    enc_pair(make_float2(f.z, f.w), o.y, o.w);
    return o;
}

// ================= k1: degree + in-count =================
__global__ void degcnt_kernel(const int* __restrict__ src, const int* __restrict__ dst, int E) {
    int e = blockIdx.x * blockDim.x + threadIdx.x;
    if (e < E) {
        atomicAdd(&g_deg[src[e]], 1.0f);
        atomicAdd(&g_rcnt[dst[e]], 1);
    }
}
// ================= k2: per-block inclusive scans =================
__global__ void scan1_kernel(int n) {
    __shared__ int sm[SCAN_B];
    int i = blockIdx.x * SCAN_B + threadIdx.x;
    int v = (i < n) ? g_rcnt[i] : 0;
    sm[threadIdx.x] = v;
    __syncthreads();
    for (int off = 1; off < SCAN_B; off <<= 1) {
        int t = (threadIdx.x >= off) ? sm[threadIdx.x - off] : 0;
        __syncthreads();
        sm[threadIdx.x] += t;
        __syncthreads();
    }
    if (i < n) g_incl[i] = sm[threadIdx.x];
    if (threadIdx.x == SCAN_B - 1) g_part[blockIdx.x] = sm[threadIdx.x];
}
// ================= k3: partial-scan (redundant per block) + rowptr + dinv ========
__global__ void scan23_kernel(int n, int nb) {
    __shared__ int pre[128];            // exclusive prefix of partials
    const int t = threadIdx.x;
    if (t < 32) {
        int run = 0;
#pragma unroll
        for (int j = 0; j < 4; ++j) {
            int idx = j * 32 + t;
            int v0 = (idx < nb) ? g_part[idx] : 0;
            int v = v0;
#pragma unroll
            for (int o = 1; o < 32; o <<= 1) {
                int u = __shfl_up_sync(0xffffffffu, v, o);
                if (t >= o) v += u;
            }
            pre[idx] = v - v0 + run;
            run += __shfl_sync(0xffffffffu, v, 31);
        }
    }
    __syncthreads();
    int i = blockIdx.x * blockDim.x + t;
    if (i < n) {
        g_rowptr[i + 1] = g_incl[i] + pre[i >> 10];
        float d = g_deg[i];
        g_dinv[i] = (d > 0.0f) ? rsqrtf(d) : 0.0f;
    }
    if (i == 0) g_rowptr[0] = 0;
}
// ================= k4: pure CSR fill (profiled slot) =================
__global__ void fill_kernel(const int* __restrict__ src, const int* __restrict__ dst, int E) {
    int e = blockIdx.x * blockDim.x + threadIdx.x;
    if (e >= E) return;
    int d = dst[e], s = src[e];
    int p = g_rowptr[d] + atomicAdd(&g_fill[d], 1);
    float w = -g_dinv[s] * g_dinv[d];
    g_csrent[p] = make_int2(s, __float_as_int(w));
}
// ================= k5: X -> interleaved planes =================
__global__ void xenc_kernel(const float4* __restrict__ X, int n) {
    int idx = blockIdx.x * blockDim.x + threadIdx.x;
    if (idx >= n * 32) return;
    int row = idx >> 5;
    int c4  = (idx & 31) << 2;
    float4 v = __ldg(&X[idx]);
    uint32_t h0, l0, h1, l1;
    enc_pair(make_float2(v.x, v.y), h0, l0);
    enc_pair(make_float2(v.z, v.w), h1, l1);
    char* xr = (char*)g_X + (size_t)row * 512;
    int p0 = posu32(c4), p1 = posu32(c4 + 2);
    *(uint32_t*)(xr + p0)     = h0;
    *(uint32_t*)(xr + p0 + 8) = l0;
    *(uint32_t*)(xr + p1)     = h1;
    *(uint32_t*)(xr + p1 + 8) = l1;
}

// ================= CSR propagation: one warp per row, 8-wide unroll ============
__global__ void __launch_bounds__(256) prop_csr_kernel(
    const uint4* __restrict__ X, uint4* __restrict__ O, int n) {
    int gw = (blockIdx.x * blockDim.x + threadIdx.x) >> 5;
    if (gw >= n) return;
    int lane = threadIdx.x & 31;
    int p    = __ldg(&g_rowptr[gw]);
    int end  = __ldg(&g_rowptr[gw + 1]);
    float4 acc = make_float4(0.f, 0.f, 0.f, 0.f);
    for (; p + 7 < end; p += 8) {
        int2 e[8];
        uint4 v[8];
#pragma unroll
        for (int i = 0; i < 8; ++i) e[i] = __ldg(&g_csrent[p + i]);
#pragma unroll
        for (int i = 0; i < 8; ++i) v[i] = __ldg(&X[(size_t)e[i].x * 32 + lane]);
#pragma unroll
        for (int i = 0; i < 8; ++i) {
            float w = __int_as_float(e[i].y);
            float4 f = dec4(v[i]);
            acc.x = fmaf(w, f.x, acc.x);
            acc.y = fmaf(w, f.y, acc.y);
            acc.z = fmaf(w, f.z, acc.z);
            acc.w = fmaf(w, f.w, acc.w);
        }
    }
    for (; p < end; ++p) {
        int2 e = __ldg(&g_csrent[p]);
        float w = __int_as_float(e.y);
        float4 f = dec4(__ldg(&X[(size_t)e.x * 32 + lane]));
        acc.x = fmaf(w, f.x, acc.x);
        acc.y = fmaf(w, f.y, acc.y);
        acc.z = fmaf(w, f.z, acc.z);
        acc.w = fmaf(w, f.w, acc.w);
    }
    O[(size_t)gw * 32 + lane] = enc4(acc);
}

// ================= weight pre-conversion (combined Chebyshev weights) ============
__global__ void wcvt_kernel(const float* __restrict__ W1, const float* __restrict__ W2,
                            const float* __restrict__ W3, uint32_t* __restrict__ out) {
    int e = blockIdx.x * blockDim.x + threadIdx.x;
    if (e >= 9 * 8192) return;
    int L  = e / 24576;
    int r  = e % 24576;
    int s  = r >> 13;
    int rr = r & 8191;
    int p  = rr >> 7;
    int nn = rr & 127;
    const float* W = (L == 0) ? W1 : (L == 1) ? W2 : W3;
    int k = 2 * p;
    float v0, v1;
    if (s == 0) {
        v0 = W[k * 128 + nn]       - W[2 * 16384 + k * 128 + nn];
        v1 = W[(k + 1) * 128 + nn] - W[2 * 16384 + (k + 1) * 128 + nn];
    } else if (s == 1) {
        v0 = W[16384 + k * 128 + nn];
        v1 = W[16384 + (k + 1) * 128 + nn];
    } else {
        v0 = 2.0f * W[2 * 16384 + k * 128 + nn];
        v1 = 2.0f * W[2 * 16384 + (k + 1) * 128 + nn];
    }
    uint32_t h, l;
    enc_pair(make_float2(v0, v1), h, l);
    char* o = (char*)out + ((size_t)(L * 3 + s) * 128 + nn) * 512;
    int pos = posu32(k);
    *(uint32_t*)(o + pos)     = h;
    *(uint32_t*)(o + pos + 8) = l;
}

// ================= pipelined bf16 mma.sync GEMM =================
#define HP 320
#define SM_GEMM (4 * 128 * HP)

__device__ __forceinline__ uint32_t smem_u32(const void* p) {
    uint32_t a;
    asm("{ .reg .u64 t; cvta.to.shared.u64 t, %1; cvt.u32.u64 %0, t; }" : "=r"(a) : "l"(p));
    return a;
}
__device__ __forceinline__ void mma_bf16(float& d0, float& d1, float& d2, float& d3,
                                         uint32_t a0, uint32_t a1, uint32_t a2, uint32_t a3,
                                         uint32_t b0, uint32_t b1) {
    asm volatile("mma.sync.aligned.m16n8k16.row.col.f32.bf16.bf16.f32 "
                 "{%0,%1,%2,%3}, {%4,%5,%6,%7}, {%8,%9}, {%0,%1,%2,%3};"
                 : "+f"(d0), "+f"(d1), "+f"(d2), "+f"(d3)
                 : "r"(a0), "r"(a1), "r"(a2), "r"(a3), "r"(b0), "r"(b1));
}

template <int MODE>
__global__ void __launch_bounds__(256, 1) gemm_mma_kernel(
    const uint32_t* __restrict__ A0, const uint32_t* __restrict__ A1,
    const uint32_t* __restrict__ A2,
    const uint32_t* __restrict__ Wc, const float* __restrict__ bias,
    uint32_t* __restrict__ OUT, const int* __restrict__ batch, int n)
{
    extern __shared__ __align__(16) char smem[];
    const int tid  = threadIdx.x;
    const int wid  = tid >> 5;
    const int lane = tid & 31;
    const int wm   = wid & 3;
    const int wn   = wid >> 2;
    const int row0 = blockIdx.x * 128;

    float acc[2][8][4];
#pragma unroll
    for (int i = 0; i < 2; ++i)
#pragma unroll
        for (int j = 0; j < 8; ++j)
#pragma unroll
            for (int c = 0; c < 4; ++c) acc[i][j][c] = 0.0f;

    const uint32_t smA[2] = { smem_u32(smem),                smem_u32(smem + 128 * HP) };
    const uint32_t smW[2] = { smem_u32(smem + 2 * 128 * HP), smem_u32(smem + 3 * 128 * HP) };
    const uint32_t* Asrc[3] = { A0, A1, A2 };

    auto stage = [&](int c) {
        int s = c >> 1, h = c & 1;
        const char* asrc = (const char*)Asrc[s] + (size_t)row0 * 512 + h * 256;
        const char* wsrc = (const char*)Wc + (size_t)s * 65536 + h * 256;
        uint32_t dA = smA[c & 1], dW = smW[c & 1];
#pragma unroll
        for (int i = 0; i < 8; ++i) {
            int q = i * 256 + tid;
            int r = q >> 4, g = q & 15;
            uint32_t od = (uint32_t)(r * HP + g * 16);
            size_t  so = (size_t)r * 512 + g * 16;
            asm volatile("cp.async.cg.shared.global [%0], [%1], 16;" :: "r"(dA + od), "l"(asrc + so));
            asm volatile("cp.async.cg.shared.global [%0], [%1], 16;" :: "r"(dW + od), "l"(wsrc + so));
        }
        asm volatile("cp.async.commit_group;" ::: "memory");
    };

    stage(0);
    stage(1);

#pragma unroll
    for (int c = 0; c < 6; ++c) {
        if (c < 5) asm volatile("cp.async.wait_group 1;" ::: "memory");
        else       asm volatile("cp.async.wait_group 0;" ::: "memory");
        __syncthreads();
        {
            const char* a0 = smem + (size_t)(c & 1) * 128 * HP
                           + (wm * 32 + (lane >> 2)) * HP + (lane & 3) * 16;
            const char* b0 = smem + (size_t)(2 + (c & 1)) * 128 * HP
                           + (wn * 64 + (lane >> 2)) * HP + (lane & 3) * 16;
#pragma unroll
            for (int g = 0; g < 4; ++g) {
                const int go = g * 64;
                uint4 va[4], vb[8];
#pragma unroll
                for (int r = 0; r < 4; ++r)
                    va[r] = *(const uint4*)(a0 + r * 8 * HP + go);
#pragma unroll
                for (int j = 0; j < 8; ++j)
                    vb[j] = *(const uint4*)(b0 + j * 8 * HP + go);
#pragma unroll
                for (int j = 0; j < 8; ++j) {
                    mma_bf16(acc[0][j][0], acc[0][j][1], acc[0][j][2], acc[0][j][3],
                             va[0].x, va[1].x, va[0].y, va[1].y, vb[j].x, vb[j].y);
                    mma_bf16(acc[1][j][0], acc[1][j][1], acc[1][j][2], acc[1][j][3],
                             va[2].x, va[3].x, va[2].y, va[3].y, vb[j].x, vb[j].y);
                    mma_bf16(acc[0][j][0], acc[0][j][1], acc[0][j][2], acc[0][j][3],
                             va[0].z, va[1].z, va[0].w, va[1].w, vb[j].x, vb[j].y);
                    mma_bf16(acc[1][j][0], acc[1][j][1], acc[1][j][2], acc[1][j][3],
                             va[2].z, va[3].z, va[2].w, va[3].w, vb[j].x, vb[j].y);
                    mma_bf16(acc[0][j][0], acc[0][j][1], acc[0][j][2], acc[0][j][3],
                             va[0].x, va[1].x, va[0].y, va[1].y, vb[j].z, vb[j].w);
                    mma_bf16(acc[1][j][0], acc[1][j][1], acc[1][j][2], acc[1][j][3],
                             va[2].x, va[3].x, va[2].y, va[3].y, vb[j].z, vb[j].w);
                }
            }
        }
        __syncthreads();
        if (c + 2 < 6) stage(c + 2);
    }

    // ---- epilogue ----
#pragma unroll
    for (int i = 0; i < 2; ++i) {
        int r0 = row0 + wm * 32 + i * 16 + (lane >> 2);
        int r1 = r0 + 8;
        int g0 = 0, g1 = 0;
        if (MODE == 2) {
            if (r0 < n) g0 = __ldg(&batch[r0]);
            if (r1 < n) g1 = __ldg(&batch[r1]);
        }
#pragma unroll
        for (int j = 0; j < 8; ++j) {
            int col = wn * 64 + j * 8 + (lane & 3) * 2;
            float2 bv = __ldg((const float2*)&bias[col]);
            float2 o0 = make_float2(acc[i][j][0] + bv.x, acc[i][j][1] + bv.y);
            float2 o1 = make_float2(acc[i][j][2] + bv.x, acc[i][j][3] + bv.y);
            if (MODE == 0) {
                o0.x = fmaxf(o0.x, 0.f); o0.y = fmaxf(o0.y, 0.f);
                o1.x = fmaxf(o1.x, 0.f); o1.y = fmaxf(o1.y, 0.f);
                int pos = posu32(col);
                uint32_t h, l;
                if (r0 < n) {
                    enc_pair(o0, h, l);
                    char* orow = (char*)OUT + (size_t)r0 * 512;
                    *(uint32_t*)(orow + pos)     = h;
                    *(uint32_t*)(orow + pos + 8) = l;
                }
                if (r1 < n) {
                    enc_pair(o1, h, l);
                    char* orow = (char*)OUT + (size_t)r1 * 512;
                    *(uint32_t*)(orow + pos)     = h;
                    *(uint32_t*)(orow + pos + 8) = l;
                }
            } else {
                if (r0 < n) {
                    float* p = &g_sums[g0 * FDIM + col];
                    asm volatile("red.global.add.v2.f32 [%0], {%1,%2};"
                                 :: "l"(p), "f"(o0.x), "f"(o0.y) : "memory");
                }
                if (r1 < n) {
                    float* p = &g_sums[g1 * FDIM + col];
                    asm volatile("red.global.add.v2.f32 [%0], {%1,%2};"
                                 :: "l"(p), "f"(o1.x), "f"(o1.y) : "memory");
                }
            }
        }
    }
}

// ================= classifier =================
__global__ void final_kernel(const int* __restrict__ batch, int n,
                             const float* __restrict__ Wl, const float* __restrict__ bl,
                             float* __restrict__ out, int ngraphs) {
    int tid = blockIdx.x * blockDim.x + threadIdx.x;
    if (tid >= ngraphs * CLS) return;
    int g = tid / CLS;
    int c = tid % CLS;
    int lo = 0, hi = n;
    while (lo < hi) { int m = (lo + hi) >> 1; if (__ldg(&batch[m]) < g) lo = m + 1; else hi = m; }
    int start = lo;
    lo = start; hi = n;
    while (lo < hi) { int m = (lo + hi) >> 1; if (__ldg(&batch[m]) < g + 1) lo = m + 1; else hi = m; }
    float cnt = (float)(lo - start);
    float s = 0.0f;
    const float* sp = &g_sums[g * FDIM];
#pragma unroll 16
    for (int d = 0; d < FDIM; ++d) s = fmaf(sp[d], Wl[d * CLS + c], s);
    out[g * CLS + c] = s / fmaxf(cnt, 1.0f) + bl[c];
}

// ---------------------------------------------------------------
extern "C" void kernel_launch(void* const* d_in, const int* in_sizes, int n_in,
                              void* d_out, int out_size) {
    const float* x   = (const float*)d_in[0];
    const int*   ei  = (const int*)  d_in[1];
    const int*   bat = (const int*)  d_in[2];
    const float* W1  = (const float*)d_in[3];
    const float* b1  = (const float*)d_in[4];
    const float* W2  = (const float*)d_in[5];
    const float* b2  = (const float*)d_in[6];
    const float* W3  = (const float*)d_in[7];
    const float* b3  = (const float*)d_in[8];
    const float* Wl  = (const float*)d_in[9];
    const float* bl  = (const float*)d_in[10];
    float* out = (float*)d_out;

    const int n = in_sizes[0] / FDIM;
    const int E = in_sizes[1] / 2;
    const int G = out_size / CLS;
    const int* src = ei;
    const int* dst = ei + E;
    const int ntiles = (n + 127) / 128;

    float *deg, *sums;
    int *rcnt, *fill;
    uint32_t *X, *T1, *Y, *H1, *H2, *Wc;
    cudaGetSymbolAddress((void**)&deg,  g_deg);
    cudaGetSymbolAddress((void**)&rcnt, g_rcnt);
    cudaGetSymbolAddress((void**)&fill, g_fill);
    cudaGetSymbolAddress((void**)&X,  g_X);
    cudaGetSymbolAddress((void**)&T1, g_T1);
    cudaGetSymbolAddress((void**)&Y,  g_Y);
    cudaGetSymbolAddress((void**)&H1, g_H1);
    cudaGetSymbolAddress((void**)&H2, g_H2);
    cudaGetSymbolAddress((void**)&sums, g_sums);
    cudaGetSymbolAddress((void**)&Wc,   g_Wc);

    cudaFuncSetAttribute(gemm_mma_kernel<0>, cudaFuncAttributeMaxDynamicSharedMemorySize, SM_GEMM);
    cudaFuncSetAttribute(gemm_mma_kernel<2>, cudaFuncAttributeMaxDynamicSharedMemorySize, SM_GEMM);

    const int TB = 256;

    cudaMemsetAsync(deg,  0, (size_t)n * sizeof(float));
    cudaMemsetAsync(rcnt, 0, (size_t)n * sizeof(int));
    cudaMemsetAsync(fill, 0, (size_t)n * sizeof(int));
    cudaMemsetAsync(sums, 0, (size_t)G * FDIM * sizeof(float));

    // prepass: fill_kernel is launch #4 (ncu slot)
    degcnt_kernel<<<(E + TB - 1) / TB, TB>>>(src, dst, E);
    const int nb = (n + SCAN_B - 1) / SCAN_B;
    scan1_kernel<<<nb, SCAN_B>>>(n);
    scan23_kernel<<<(n + TB - 1) / TB, TB>>>(n, nb);
    fill_kernel<<<(E + TB - 1) / TB, TB>>>(src, dst, E);
    xenc_kernel<<<(n * 32 + TB - 1) / TB, TB>>>((const float4*)x, n);
    wcvt_kernel<<<(9 * 8192 + TB - 1) / TB, TB>>>(W1, W2, W3, Wc);

    const int propBlocks = (n * 32 + TB - 1) / TB;

    // layer 1
    prop_csr_kernel<<<propBlocks, TB>>>((const uint4*)X, (uint4*)T1, n);
    prop_csr_kernel<<<propBlocks, TB>>>((const uint4*)T1, (uint4*)Y, n);
    gemm_mma_kernel<0><<<ntiles, 256, SM_GEMM>>>(X, T1, Y, Wc, b1, H1, nullptr, n);
    // layer 2
    prop_csr_kernel<<<propBlocks, TB>>>((const uint4*)H1, (uint4*)T1, n);
    prop_csr_kernel<<<propBlocks, TB>>>((const uint4*)T1, (uint4*)Y, n);
    gemm_mma_kernel<0><<<ntiles, 256, SM_GEMM>>>(H1, T1, Y, Wc + (size_t)3 * 16384, b2, H2, nullptr, n);
    // layer 3 (pool fused)
    prop_csr_kernel<<<propBlocks, TB>>>((const uint4*)H2, (uint4*)T1, n);
    prop_csr_kernel<<<propBlocks, TB>>>((const uint4*)T1, (uint4*)Y, n);
    gemm_mma_kernel<2><<<ntiles, 256, SM_GEMM>>>(H2, T1, Y, Wc + (size_t)6 * 16384, b3, nullptr, bat, n);

    // classifier
    final_kernel<<<(G * CLS + TB - 1) / TB, TB>>>(bat, n, Wl, bl, out, G);
}